// round 2
// baseline (speedup 1.0000x reference)
#include <cuda_runtime.h>
#include <math.h>

#define H 128
#define KEXT 144          // 128 h-features + 9 ea_sum + (deg+1) + 1 + 5 pad
#define NG 256
#define NT 40
#define MAXN 50048
#define BN_EPS 1e-5f

// ---------------- scratch (device globals; no allocations allowed) ----------
__device__ float g_h[MAXN * H];          // current node features (in-place across layers)
__device__ float g_agg[MAXN * KEXT];     // extended aggregation matrix
__device__ float g_z[MAXN * 2 * H];      // post-BN/ReLU hidden
__device__ float g_easum[MAXN * 9];      // segment-sum of edge_attr by dst
__device__ int   g_deg[MAXN];
__device__ float g_w1ext[KEXT * 2 * H];  // extended W1 (rebuilt per layer)
__device__ float g_scale[2 * H];
__device__ float g_shift[2 * H];
__device__ float g_pool[NG * H];
__device__ int   g_cnt[NG];

// ---------------- helpers ---------------------------------------------------
__device__ __forceinline__ void red_add_v4(float* p, float4 v) {
    asm volatile("red.global.add.v4.f32 [%0], {%1,%2,%3,%4};"
                 :: "l"(p), "f"(v.x), "f"(v.y), "f"(v.z), "f"(v.w) : "memory");
}

// ---------------- kernels ----------------------------------------------------
__global__ void zero_kernel(int N) {
    int i = blockIdx.x * blockDim.x + threadIdx.x;
    int tot = N * 9;
    if (i < tot) g_easum[i] = 0.f;
    if (i < N)   g_deg[i] = 0;
    if (i < NG * H) g_pool[i] = 0.f;
    if (i < NG)  g_cnt[i] = 0;
}

__global__ void init_h0(const int* __restrict__ x, const float* __restrict__ emb,
                        const int* __restrict__ batch, int N) {
    int t = blockIdx.x * blockDim.x + threadIdx.x;
    if (t >= N * 32) return;
    int n = t >> 5, j = t & 31;
    float4 v = *(const float4*)(emb + (size_t)x[n] * H + j * 4);
    *(float4*)(g_h + (size_t)n * H + j * 4) = v;
    if (j == 0) atomicAdd(&g_cnt[batch[n]], 1);
}

__global__ void edge_presum(const int* __restrict__ ei, const float* __restrict__ ea, int E) {
    int e = blockIdx.x * blockDim.x + threadIdx.x;
    if (e >= E) return;
    int d = ei[e];                       // dst (segment id)
    const float* a = ea + (size_t)e * 9;
    float* s = g_easum + (size_t)d * 9;
#pragma unroll
    for (int j = 0; j < 9; j++) atomicAdd(s + j, a[j]);
    atomicAdd(&g_deg[d], 1);
}

// Build extended W1 and BN fold (per layer)
__global__ void prep_layer(const float* __restrict__ enc_w, const float* __restrict__ enc_b,
                           const float* __restrict__ w1,    const float* __restrict__ b1,
                           const float* __restrict__ gamma, const float* __restrict__ beta,
                           const float* __restrict__ mean,  const float* __restrict__ var,
                           const int* __restrict__ sli_p,   const int* __restrict__ slt_p) {
    int k = blockIdx.x;      // 0..143
    int c = threadIdx.x;     // 0..255
    float v;
    if (k < 128) {
        v = w1[k * 256 + c];
    } else if (k < 139) {
        int j = k - 128;
        int sli = *sli_p;
        float slt = (float)(*slt_p);
        float s = 0.f;
        for (int i = 0; i < 128; i++) {
            float f;
            if (j < 9)       f = enc_w[j * 128 + i];
            else if (j == 9) f = enc_b[i];
            else             f = slt * enc_w[sli * 128 + i];
            s += f * w1[(128 + i) * 256 + c];
        }
        v = s;
    } else {
        v = 0.f;
    }
    g_w1ext[k * 256 + c] = v;
    if (k == 0) {
        float sc = gamma[c] * rsqrtf(var[c] + BN_EPS);
        g_scale[c] = sc;
        g_shift[c] = (b1[c] - mean[c]) * sc + beta[c];
    }
}

// agg rows: [h(self loop) | ea_sum | deg+1 | 1 | 0 pad]
__global__ void agg_build(int N) {
    int t = blockIdx.x * blockDim.x + threadIdx.x;
    if (t >= N * 36) return;
    int n = t / 36, q = t % 36;
    float4 v;
    if (q < 32) {
        v = *(const float4*)(g_h + (size_t)n * H + q * 4);
    } else if (q == 32) {
        const float* s = g_easum + (size_t)n * 9;
        v = make_float4(s[0], s[1], s[2], s[3]);
    } else if (q == 33) {
        const float* s = g_easum + (size_t)n * 9;
        v = make_float4(s[4], s[5], s[6], s[7]);
    } else if (q == 34) {
        v = make_float4(g_easum[(size_t)n * 9 + 8], (float)(g_deg[n] + 1), 1.f, 0.f);
    } else {
        v = make_float4(0.f, 0.f, 0.f, 0.f);
    }
    *(float4*)(g_agg + (size_t)n * KEXT + q * 4) = v;
}

// warp per edge: agg[dst][0:128] += h[src]
__global__ void spmm(const int* __restrict__ ei, int E) {
    int t = blockIdx.x * blockDim.x + threadIdx.x;
    int e = t >> 5;
    if (e >= E) return;
    int lane = t & 31;
    int dst = ei[e];
    int src = ei[E + e];
    float4 v = *(const float4*)(g_h + (size_t)src * H + lane * 4);
    red_add_v4(g_agg + (size_t)dst * KEXT + lane * 4, v);
}

// C[M,N] = epi(A[M,K] @ B[K,N]); epi: *scale[c] (opt) + shift[c] (opt), relu (opt)
__global__ void __launch_bounds__(256)
gemm_kernel(const float* __restrict__ A, const float* __restrict__ B,
            float* __restrict__ C, int M, int N, int K,
            const float* __restrict__ scale, const float* __restrict__ shift, int relu) {
    __shared__ float As[16][132];
    __shared__ float Bs[16][128];
    int bm = blockIdx.x * 128, bn = blockIdx.y * 128;
    int tid = threadIdx.x;
    int tr = tid / 16, tc = tid % 16;
    int arow = tid / 4, acol4 = (tid % 4) * 4;
    int brow = tid / 32, bcol4 = (tid % 32) * 4;
    float acc[8][8];
#pragma unroll
    for (int i = 0; i < 8; i++)
#pragma unroll
        for (int j = 0; j < 8; j++) acc[i][j] = 0.f;

    for (int k0 = 0; k0 < K; k0 += 16) {
#pragma unroll
        for (int i = 0; i < 2; i++) {
            int r = arow + i * 64;
            int gr = bm + r;
            float4 v = make_float4(0.f, 0.f, 0.f, 0.f);
            if (gr < M) v = *(const float4*)(A + (size_t)gr * K + k0 + acol4);
            As[acol4 + 0][r] = v.x;
            As[acol4 + 1][r] = v.y;
            As[acol4 + 2][r] = v.z;
            As[acol4 + 3][r] = v.w;
        }
#pragma unroll
        for (int i = 0; i < 2; i++) {
            int r = brow + i * 8;
            *(float4*)&Bs[r][bcol4] = *(const float4*)(B + (size_t)(k0 + r) * N + bn + bcol4);
        }
        __syncthreads();
#pragma unroll
        for (int k = 0; k < 16; k++) {
            float a[8], b[8];
            *(float4*)&a[0] = *(const float4*)&As[k][tr * 8];
            *(float4*)&a[4] = *(const float4*)&As[k][tr * 8 + 4];
            *(float4*)&b[0] = *(const float4*)&Bs[k][tc * 8];
            *(float4*)&b[4] = *(const float4*)&Bs[k][tc * 8 + 4];
#pragma unroll
            for (int i = 0; i < 8; i++)
#pragma unroll
                for (int j = 0; j < 8; j++) acc[i][j] += a[i] * b[j];
        }
        __syncthreads();
    }
#pragma unroll
    for (int i = 0; i < 8; i++) {
        int gr = bm + tr * 8 + i;
        if (gr >= M) break;
#pragma unroll
        for (int j = 0; j < 8; j++) {
            int gc = bn + tc * 8 + j;
            float v = acc[i][j];
            if (scale) v *= scale[gc];
            if (shift) v += shift[gc];
            if (relu)  v = fmaxf(v, 0.f);
            C[(size_t)gr * N + gc] = v;
        }
    }
}

__global__ void pool_kernel(const int* __restrict__ batch, int N) {
    int t = blockIdx.x * blockDim.x + threadIdx.x;
    if (t >= N * 32) return;
    int n = t >> 5, j = t & 31;
    float4 v = *(const float4*)(g_h + (size_t)n * H + j * 4);
    int g = batch[n];
    red_add_v4(g_pool + (size_t)g * H + j * 4, v);
}

__global__ void pred_kernel(const float* __restrict__ pw, const float* __restrict__ pb,
                            float* __restrict__ out) {
    int t = blockIdx.x * blockDim.x + threadIdx.x;
    if (t >= NG * NT) return;
    int g = t / NT, c = t % NT;
    const float* pr = g_pool + (size_t)g * H;
    float s = 0.f;
#pragma unroll 8
    for (int k = 0; k < H; k++)
        s += pr[k] * (pw[k * NT + c] + pw[(k + H) * NT + c]);
    float cnt = fmaxf((float)g_cnt[g], 1.f);
    out[t] = s / cnt + pb[c];
}

// ---------------- launch -----------------------------------------------------
extern "C" void kernel_launch(void* const* d_in, const int* in_sizes, int n_in,
                              void* d_out, int out_size) {
    const int*   x        = (const int*)  d_in[0];
    const int*   ei       = (const int*)  d_in[1];
    const float* ea       = (const float*)d_in[2];
    const int*   batch    = (const int*)  d_in[3];
    const int*   sli      = (const int*)  d_in[4];
    const int*   slt      = (const int*)  d_in[5];
    const float* node_emb = (const float*)d_in[6];
    const float* L[2][10];
    for (int l = 0; l < 2; l++)
        for (int j = 0; j < 10; j++)
            L[l][j] = (const float*)d_in[7 + l * 10 + j];
    // per layer: 0 enc_w, 1 enc_b, 2 w1, 3 b1, 4 gamma, 5 beta, 6 mean, 7 var, 8 w2, 9 b2
    const float* pred_w = (const float*)d_in[27];
    const float* pred_b = (const float*)d_in[28];
    float* out = (float*)d_out;

    int N = in_sizes[0];
    int E = in_sizes[1] / 2;

    // CRITICAL: resolve the DEVICE addresses of __device__ symbols. Passing the
    // symbol name directly from host code passes the host shadow (which the GPU
    // can dereference via ATS on GB300 -> silent garbage, no fault).
    float *p_agg, *p_w1ext, *p_z, *p_h, *p_scale, *p_shift;
    cudaGetSymbolAddress((void**)&p_agg,   g_agg);
    cudaGetSymbolAddress((void**)&p_w1ext, g_w1ext);
    cudaGetSymbolAddress((void**)&p_z,     g_z);
    cudaGetSymbolAddress((void**)&p_h,     g_h);
    cudaGetSymbolAddress((void**)&p_scale, g_scale);
    cudaGetSymbolAddress((void**)&p_shift, g_shift);

    zero_kernel<<<(N * 9 + 255) / 256, 256>>>(N);
    init_h0<<<(N * 32 + 255) / 256, 256>>>(x, node_emb, batch, N);
    edge_presum<<<(E + 255) / 256, 256>>>(ei, ea, E);

    for (int l = 0; l < 2; l++) {
        prep_layer<<<KEXT, 256>>>(L[l][0], L[l][1], L[l][2], L[l][3], L[l][4],
                                  L[l][5], L[l][6], L[l][7], sli, slt);
        agg_build<<<(N * 36 + 255) / 256, 256>>>(N);
        spmm<<<(E * 32 + 255) / 256, 256>>>(ei, E);
        // z = relu(bn(agg_ext @ w1_ext))   [N,144]x[144,256]
        gemm_kernel<<<dim3((N + 127) / 128, 2), 256>>>(
            p_agg, p_w1ext, p_z, N, 256, KEXT, p_scale, p_shift, 1);
        // h = z @ w2 + b2 (+relu for layer 0)   [N,256]x[256,128]
        gemm_kernel<<<dim3((N + 127) / 128, 1), 256>>>(
            p_z, L[l][8], p_h, N, 128, 256, nullptr, L[l][9], l == 0 ? 1 : 0);
    }

    pool_kernel<<<(N * 32 + 255) / 256, 256>>>(batch, N);
    pred_kernel<<<(NG * NT + 127) / 128, 128>>>(pred_w, pred_b, out);
}

// round 3
// speedup vs baseline: 1.1524x; 1.1524x over previous
#include <cuda_runtime.h>
#include <math.h>

#define H 128
#define KEXT 144          // 128 h-features + 9 ea_sum + (deg+1) + 1 + 5 pad
#define NG 256
#define NT 40
#define MAXN 50048
#define BN_EPS 1e-5f

// ---------------- scratch (device globals; no allocations allowed) ----------
__device__ float g_h[MAXN * H];
__device__ float g_agg[MAXN * KEXT];
__device__ float g_z[MAXN * 2 * H];
__device__ float g_easum[MAXN * 9];
__device__ int   g_deg[MAXN];
__device__ float g_w1ext[KEXT * 2 * H];
__device__ float g_scale[2 * H];
__device__ float g_shift[2 * H];
__device__ float g_pool[NG * H];
__device__ int   g_cnt[NG];

// ---------------- helpers ---------------------------------------------------
__device__ __forceinline__ void red_add_v4(float* p, float4 v) {
    asm volatile("red.global.add.v4.f32 [%0], {%1,%2,%3,%4};"
                 :: "l"(p), "f"(v.x), "f"(v.y), "f"(v.z), "f"(v.w) : "memory");
}

// ---------------- kernels ----------------------------------------------------
__global__ void zero_kernel(int N) {
    int i = blockIdx.x * blockDim.x + threadIdx.x;
    int tot = N * 9;
    if (i < tot) g_easum[i] = 0.f;
    if (i < N)   g_deg[i] = 0;
    if (i < NG * H) g_pool[i] = 0.f;
    if (i < NG)  g_cnt[i] = 0;
}

__global__ void init_h0(const int* __restrict__ x, const float* __restrict__ emb,
                        const int* __restrict__ batch, int N) {
    int t = blockIdx.x * blockDim.x + threadIdx.x;
    if (t >= N * 32) return;
    int n = t >> 5, j = t & 31;
    float4 v = *(const float4*)(emb + (size_t)x[n] * H + j * 4);
    *(float4*)(g_h + (size_t)n * H + j * 4) = v;
    if (j == 0) atomicAdd(&g_cnt[batch[n]], 1);
}

__global__ void edge_presum(const int* __restrict__ ei, const float* __restrict__ ea, int E) {
    int e = blockIdx.x * blockDim.x + threadIdx.x;
    if (e >= E) return;
    int d = ei[e];
    const float* a = ea + (size_t)e * 9;
    float* s = g_easum + (size_t)d * 9;
#pragma unroll
    for (int j = 0; j < 9; j++) atomicAdd(s + j, a[j]);
    atomicAdd(&g_deg[d], 1);
}

// Build extended W1 and BN fold. Blocks 0-127: copy. Blocks 128-138: rank-11
// fold rows via smem-cached f vector + unrolled MLP-heavy reduction.
__global__ void prep_layer(const float* __restrict__ enc_w, const float* __restrict__ enc_b,
                           const float* __restrict__ w1,    const float* __restrict__ b1,
                           const float* __restrict__ gamma, const float* __restrict__ beta,
                           const float* __restrict__ mean,  const float* __restrict__ var,
                           const int* __restrict__ sli_p,   const int* __restrict__ slt_p) {
    int k = blockIdx.x;      // 0..143
    int c = threadIdx.x;     // 0..255
    if (k < 128) {
        g_w1ext[k * 256 + c] = w1[k * 256 + c];
    } else if (k < 139) {
        __shared__ float f[128];
        int j = k - 128;
        if (c < 128) {
            float fv;
            if (j < 9)       fv = enc_w[j * 128 + c];
            else if (j == 9) fv = enc_b[c];
            else             fv = (float)(*slt_p) * enc_w[(*sli_p) * 128 + c];
            f[c] = fv;
        }
        __syncthreads();
        float s = 0.f;
        const float* wb = w1 + 128 * 256 + c;
#pragma unroll 16
        for (int i = 0; i < 128; i++)
            s += f[i] * wb[i * 256];
        g_w1ext[k * 256 + c] = s;
    } else {
        g_w1ext[k * 256 + c] = 0.f;
    }
    if (k == 0) {
        float sc = gamma[c] * rsqrtf(var[c] + BN_EPS);
        g_scale[c] = sc;
        g_shift[c] = (b1[c] - mean[c]) * sc + beta[c];
    }
}

// agg rows: [h(self loop) | ea_sum | deg+1 | 1 | 0 pad]
__global__ void agg_build(int N) {
    int t = blockIdx.x * blockDim.x + threadIdx.x;
    if (t >= N * 36) return;
    int n = t / 36, q = t % 36;
    float4 v;
    if (q < 32) {
        v = *(const float4*)(g_h + (size_t)n * H + q * 4);
    } else if (q == 32) {
        const float* s = g_easum + (size_t)n * 9;
        v = make_float4(s[0], s[1], s[2], s[3]);
    } else if (q == 33) {
        const float* s = g_easum + (size_t)n * 9;
        v = make_float4(s[4], s[5], s[6], s[7]);
    } else if (q == 34) {
        v = make_float4(g_easum[(size_t)n * 9 + 8], (float)(g_deg[n] + 1), 1.f, 0.f);
    } else {
        v = make_float4(0.f, 0.f, 0.f, 0.f);
    }
    *(float4*)(g_agg + (size_t)n * KEXT + q * 4) = v;
}

// warp per edge: agg[dst][0:128] += h[src]
__global__ void spmm(const int* __restrict__ ei, int E) {
    int t = blockIdx.x * blockDim.x + threadIdx.x;
    int e = t >> 5;
    if (e >= E) return;
    int lane = t & 31;
    int dst = __ldg(ei + e);
    int src = __ldg(ei + E + e);
    float4 v = *(const float4*)(g_h + (size_t)src * H + lane * 4);
    red_add_v4(g_agg + (size_t)dst * KEXT + lane * 4, v);
}

// C[M,N] = epi(A[M,K] @ B[K,N]); double-buffered 128x128x16 tiles, 8x8/thread.
__global__ void __launch_bounds__(256, 2)
gemm_kernel(const float* __restrict__ A, const float* __restrict__ B,
            float* __restrict__ C, int M, int N, int K,
            const float* __restrict__ scale, const float* __restrict__ shift, int relu) {
    __shared__ float As[2][16][132];
    __shared__ float Bs[2][16][128];
    int bm = blockIdx.x * 128, bn = blockIdx.y * 128;
    int tid = threadIdx.x;
    int tr = tid / 16, tc = tid % 16;
    int arow = tid / 4, acol4 = (tid % 4) * 4;
    int brow = tid / 32, bcol4 = (tid % 32) * 4;

    float acc[8][8];
#pragma unroll
    for (int i = 0; i < 8; i++)
#pragma unroll
        for (int j = 0; j < 8; j++) acc[i][j] = 0.f;

    float4 ra[2], rb[2];
    const float4 zero4 = make_float4(0.f, 0.f, 0.f, 0.f);

    // prefetch chunk 0
    {
        int gr0 = bm + arow, gr1 = bm + arow + 64;
        ra[0] = (gr0 < M) ? *(const float4*)(A + (size_t)gr0 * K + acol4) : zero4;
        ra[1] = (gr1 < M) ? *(const float4*)(A + (size_t)gr1 * K + acol4) : zero4;
        rb[0] = *(const float4*)(B + (size_t)brow * N + bn + bcol4);
        rb[1] = *(const float4*)(B + (size_t)(brow + 8) * N + bn + bcol4);
    }
    // store chunk 0
    {
        As[0][acol4 + 0][arow] = ra[0].x; As[0][acol4 + 1][arow] = ra[0].y;
        As[0][acol4 + 2][arow] = ra[0].z; As[0][acol4 + 3][arow] = ra[0].w;
        As[0][acol4 + 0][arow + 64] = ra[1].x; As[0][acol4 + 1][arow + 64] = ra[1].y;
        As[0][acol4 + 2][arow + 64] = ra[1].z; As[0][acol4 + 3][arow + 64] = ra[1].w;
        *(float4*)&Bs[0][brow][bcol4] = rb[0];
        *(float4*)&Bs[0][brow + 8][bcol4] = rb[1];
    }
    __syncthreads();

    int nch = K / 16;
    for (int c = 0; c < nch; c++) {
        int cur = c & 1;
        if (c + 1 < nch) {
            int k0 = (c + 1) * 16;
            int gr0 = bm + arow, gr1 = bm + arow + 64;
            ra[0] = (gr0 < M) ? *(const float4*)(A + (size_t)gr0 * K + k0 + acol4) : zero4;
            ra[1] = (gr1 < M) ? *(const float4*)(A + (size_t)gr1 * K + k0 + acol4) : zero4;
            rb[0] = *(const float4*)(B + (size_t)(k0 + brow) * N + bn + bcol4);
            rb[1] = *(const float4*)(B + (size_t)(k0 + brow + 8) * N + bn + bcol4);
        }
#pragma unroll
        for (int k = 0; k < 16; k++) {
            float a[8], b[8];
            *(float4*)&a[0] = *(const float4*)&As[cur][k][tr * 8];
            *(float4*)&a[4] = *(const float4*)&As[cur][k][tr * 8 + 4];
            *(float4*)&b[0] = *(const float4*)&Bs[cur][k][tc * 8];
            *(float4*)&b[4] = *(const float4*)&Bs[cur][k][tc * 8 + 4];
#pragma unroll
            for (int i = 0; i < 8; i++)
#pragma unroll
                for (int j = 0; j < 8; j++) acc[i][j] += a[i] * b[j];
        }
        if (c + 1 < nch) {
            int nxt = 1 - cur;
            As[nxt][acol4 + 0][arow] = ra[0].x; As[nxt][acol4 + 1][arow] = ra[0].y;
            As[nxt][acol4 + 2][arow] = ra[0].z; As[nxt][acol4 + 3][arow] = ra[0].w;
            As[nxt][acol4 + 0][arow + 64] = ra[1].x; As[nxt][acol4 + 1][arow + 64] = ra[1].y;
            As[nxt][acol4 + 2][arow + 64] = ra[1].z; As[nxt][acol4 + 3][arow + 64] = ra[1].w;
            *(float4*)&Bs[nxt][brow][bcol4] = rb[0];
            *(float4*)&Bs[nxt][brow + 8][bcol4] = rb[1];
            __syncthreads();
        }
    }

#pragma unroll
    for (int i = 0; i < 8; i++) {
        int gr = bm + tr * 8 + i;
        if (gr >= M) break;
        int gc = bn + tc * 8;
        float4 v0 = make_float4(acc[i][0], acc[i][1], acc[i][2], acc[i][3]);
        float4 v1 = make_float4(acc[i][4], acc[i][5], acc[i][6], acc[i][7]);
        if (scale) {
            const float4 s0 = *(const float4*)(scale + gc);
            const float4 s1 = *(const float4*)(scale + gc + 4);
            v0.x *= s0.x; v0.y *= s0.y; v0.z *= s0.z; v0.w *= s0.w;
            v1.x *= s1.x; v1.y *= s1.y; v1.z *= s1.z; v1.w *= s1.w;
        }
        if (shift) {
            const float4 s0 = *(const float4*)(shift + gc);
            const float4 s1 = *(const float4*)(shift + gc + 4);
            v0.x += s0.x; v0.y += s0.y; v0.z += s0.z; v0.w += s0.w;
            v1.x += s1.x; v1.y += s1.y; v1.z += s1.z; v1.w += s1.w;
        }
        if (relu) {
            v0.x = fmaxf(v0.x, 0.f); v0.y = fmaxf(v0.y, 0.f);
            v0.z = fmaxf(v0.z, 0.f); v0.w = fmaxf(v0.w, 0.f);
            v1.x = fmaxf(v1.x, 0.f); v1.y = fmaxf(v1.y, 0.f);
            v1.z = fmaxf(v1.z, 0.f); v1.w = fmaxf(v1.w, 0.f);
        }
        *(float4*)(C + (size_t)gr * N + gc) = v0;
        *(float4*)(C + (size_t)gr * N + gc + 4) = v1;
    }
}

__global__ void pool_kernel(const int* __restrict__ batch, int N) {
    int t = blockIdx.x * blockDim.x + threadIdx.x;
    if (t >= N * 32) return;
    int n = t >> 5, j = t & 31;
    float4 v = *(const float4*)(g_h + (size_t)n * H + j * 4);
    int g = batch[n];
    red_add_v4(g_pool + (size_t)g * H + j * 4, v);
}

__global__ void pred_kernel(const float* __restrict__ pw, const float* __restrict__ pb,
                            float* __restrict__ out) {
    int t = blockIdx.x * blockDim.x + threadIdx.x;
    if (t >= NG * NT) return;
    int g = t / NT, c = t % NT;
    const float* pr = g_pool + (size_t)g * H;
    float s = 0.f;
#pragma unroll 8
    for (int k = 0; k < H; k++)
        s += pr[k] * (pw[k * NT + c] + pw[(k + H) * NT + c]);
    float cnt = fmaxf((float)g_cnt[g], 1.f);
    out[t] = s / cnt + pb[c];
}

// ---------------- launch -----------------------------------------------------
extern "C" void kernel_launch(void* const* d_in, const int* in_sizes, int n_in,
                              void* d_out, int out_size) {
    const int*   x        = (const int*)  d_in[0];
    const int*   ei       = (const int*)  d_in[1];
    const float* ea       = (const float*)d_in[2];
    const int*   batch    = (const int*)  d_in[3];
    const int*   sli      = (const int*)  d_in[4];
    const int*   slt      = (const int*)  d_in[5];
    const float* node_emb = (const float*)d_in[6];
    const float* L[2][10];
    for (int l = 0; l < 2; l++)
        for (int j = 0; j < 10; j++)
            L[l][j] = (const float*)d_in[7 + l * 10 + j];
    const float* pred_w = (const float*)d_in[27];
    const float* pred_b = (const float*)d_in[28];
    float* out = (float*)d_out;

    int N = in_sizes[0];
    int E = in_sizes[1] / 2;

    // Resolve DEVICE addresses of __device__ symbols (host shadow is ATS-readable
    // on GB300 -> silent garbage if passed directly).
    float *p_agg, *p_w1ext, *p_z, *p_h, *p_scale, *p_shift;
    cudaGetSymbolAddress((void**)&p_agg,   g_agg);
    cudaGetSymbolAddress((void**)&p_w1ext, g_w1ext);
    cudaGetSymbolAddress((void**)&p_z,     g_z);
    cudaGetSymbolAddress((void**)&p_h,     g_h);
    cudaGetSymbolAddress((void**)&p_scale, g_scale);
    cudaGetSymbolAddress((void**)&p_shift, g_shift);

    zero_kernel<<<(N * 9 + 255) / 256, 256>>>(N);
    init_h0<<<(N * 32 + 255) / 256, 256>>>(x, node_emb, batch, N);
    edge_presum<<<(E + 255) / 256, 256>>>(ei, ea, E);

    for (int l = 0; l < 2; l++) {
        prep_layer<<<KEXT, 256>>>(L[l][0], L[l][1], L[l][2], L[l][3], L[l][4],
                                  L[l][5], L[l][6], L[l][7], sli, slt);
        agg_build<<<(N * 36 + 255) / 256, 256>>>(N);
        spmm<<<(E * 32 + 255) / 256, 256>>>(ei, E);
        gemm_kernel<<<dim3((N + 127) / 128, 2), 256>>>(
            p_agg, p_w1ext, p_z, N, 256, KEXT, p_scale, p_shift, 1);
        gemm_kernel<<<dim3((N + 127) / 128, 1), 256>>>(
            p_z, L[l][8], p_h, N, 128, 256, nullptr, L[l][9], l == 0 ? 1 : 0);
    }

    pool_kernel<<<(N * 32 + 255) / 256, 256>>>(batch, N);
    pred_kernel<<<(NG * NT + 127) / 128, 128>>>(pred_w, pred_b, out);
}

// round 4
// speedup vs baseline: 1.6223x; 1.4078x over previous
#include <cuda_runtime.h>
#include <math.h>
#include <stdint.h>

#define H 128
#define KEXT 144
#define NG 256
#define NT 40
#define MAXN 50048
#define BN_EPS 1e-5f

// ---------------- scratch ----------------------------------------------------
__device__ float g_h[MAXN * H];
__device__ float g_agg[MAXN * KEXT];
__device__ float g_z[MAXN * 2 * H];
__device__ float g_easum[MAXN * 9];
__device__ int   g_deg[MAXN];
__device__ float g_w1ext[KEXT * 2 * H];
__device__ float g_scale[2 * H];
__device__ float g_shift[2 * H];
__device__ float g_poolz[NG * 2 * H];   // segsum of z1 [256 graphs x 256]
__device__ float g_wf[NT * 2 * H];      // folded w2_1 @ (pred_w_top+pred_w_bot), [t][k]
__device__ float g_bf[NT];
__device__ int   g_cnt[NG];

// ---------------- helpers ---------------------------------------------------
__device__ __forceinline__ void red_add_v4(float* p, float4 v) {
    asm volatile("red.global.add.v4.f32 [%0], {%1,%2,%3,%4};"
                 :: "l"(p), "f"(v.x), "f"(v.y), "f"(v.z), "f"(v.w) : "memory");
}
__device__ __forceinline__ uint32_t f2tf32(float x) {
    uint32_t r; asm("cvt.rna.tf32.f32 %0, %1;" : "=r"(r) : "f"(x)); return r;
}
__device__ __forceinline__ void split_tf32(float v, uint32_t& hi, uint32_t& lo) {
    hi = f2tf32(v);
    float hif = __uint_as_float(hi);
    lo = f2tf32(v - hif);
}
__device__ __forceinline__ void mma_tf32(float* d, const uint32_t* a, const uint32_t* b) {
    asm volatile("mma.sync.aligned.m16n8k8.row.col.f32.tf32.tf32.f32 "
                 "{%0,%1,%2,%3},{%4,%5,%6,%7},{%8,%9},{%0,%1,%2,%3};"
                 : "+f"(d[0]), "+f"(d[1]), "+f"(d[2]), "+f"(d[3])
                 : "r"(a[0]), "r"(a[1]), "r"(a[2]), "r"(a[3]),
                   "r"(b[0]), "r"(b[1]));
}

// ---------------- small kernels ----------------------------------------------
__global__ void zero_kernel(int N) {
    int i = blockIdx.x * blockDim.x + threadIdx.x;
    if (i < N * 9)      g_easum[i] = 0.f;
    if (i < N)          g_deg[i] = 0;
    if (i < NG * 2 * H) g_poolz[i] = 0.f;
    if (i < NG)         g_cnt[i] = 0;
}

__global__ void init_h0(const int* __restrict__ x, const float* __restrict__ emb,
                        const int* __restrict__ batch, int N) {
    int t = blockIdx.x * blockDim.x + threadIdx.x;
    if (t >= N * 32) return;
    int n = t >> 5, j = t & 31;
    float4 v = *(const float4*)(emb + (size_t)x[n] * H + j * 4);
    *(float4*)(g_h + (size_t)n * H + j * 4) = v;
    if (j == 0) atomicAdd(&g_cnt[batch[n]], 1);
}

__global__ void edge_presum(const int* __restrict__ ei, const float* __restrict__ ea, int E) {
    int e = blockIdx.x * blockDim.x + threadIdx.x;
    if (e >= E) return;
    int d = ei[e];
    const float* a = ea + (size_t)e * 9;
    float* s = g_easum + (size_t)d * 9;
#pragma unroll
    for (int j = 0; j < 9; j++) atomicAdd(s + j, a[j]);
    atomicAdd(&g_deg[d], 1);
}

__global__ void prep_layer(const float* __restrict__ enc_w, const float* __restrict__ enc_b,
                           const float* __restrict__ w1,    const float* __restrict__ b1,
                           const float* __restrict__ gamma, const float* __restrict__ beta,
                           const float* __restrict__ mean,  const float* __restrict__ var,
                           const int* __restrict__ sli_p,   const int* __restrict__ slt_p) {
    int k = blockIdx.x;      // 0..143
    int c = threadIdx.x;     // 0..255
    if (k < 128) {
        g_w1ext[k * 256 + c] = w1[k * 256 + c];
    } else if (k < 139) {
        __shared__ float f[128];
        int j = k - 128;
        if (c < 128) {
            float fv;
            if (j < 9)       fv = enc_w[j * 128 + c];
            else if (j == 9) fv = enc_b[c];
            else             fv = (float)(*slt_p) * enc_w[(*sli_p) * 128 + c];
            f[c] = fv;
        }
        __syncthreads();
        float s = 0.f;
        const float* wb = w1 + 128 * 256 + c;
#pragma unroll 16
        for (int i = 0; i < 128; i++)
            s += f[i] * wb[i * 256];
        g_w1ext[k * 256 + c] = s;
    } else {
        g_w1ext[k * 256 + c] = 0.f;
    }
    if (k == 0) {
        float sc = gamma[c] * rsqrtf(var[c] + BN_EPS);
        g_scale[c] = sc;
        g_shift[c] = (b1[c] - mean[c]) * sc + beta[c];
    }
}

// Fold w2_1 and duplicated pred_w: g_wf[t][k] = sum_j w2[k][j]*(pw[j][t]+pw[j+128][t])
__global__ void prep_pred(const float* __restrict__ w2, const float* __restrict__ b2,
                          const float* __restrict__ pw, const float* __restrict__ pb) {
    int t = blockIdx.x;       // 0..39
    int k = threadIdx.x;      // 0..255
    __shared__ float pwsum[128];
    if (k < 128) pwsum[k] = pw[k * NT + t] + pw[(k + 128) * NT + t];
    __syncthreads();
    float s = 0.f;
    const float* wr = w2 + (size_t)k * 128;
#pragma unroll 16
    for (int i = 0; i < 128; i++) s += wr[i] * pwsum[i];
    g_wf[t * 256 + k] = s;
    if (k == 0) {
        float bb = 0.f;
        for (int i = 0; i < 128; i++) bb += b2[i] * pwsum[i];
        g_bf[t] = bb + pb[t];
    }
}

__global__ void agg_build(int N) {
    int t = blockIdx.x * blockDim.x + threadIdx.x;
    if (t >= N * 36) return;
    int n = t / 36, q = t % 36;
    float4 v;
    if (q < 32) {
        v = *(const float4*)(g_h + (size_t)n * H + q * 4);
    } else if (q == 32) {
        const float* s = g_easum + (size_t)n * 9;
        v = make_float4(s[0], s[1], s[2], s[3]);
    } else if (q == 33) {
        const float* s = g_easum + (size_t)n * 9;
        v = make_float4(s[4], s[5], s[6], s[7]);
    } else if (q == 34) {
        v = make_float4(g_easum[(size_t)n * 9 + 8], (float)(g_deg[n] + 1), 1.f, 0.f);
    } else {
        v = make_float4(0.f, 0.f, 0.f, 0.f);
    }
    *(float4*)(g_agg + (size_t)n * KEXT + q * 4) = v;
}

__global__ void spmm(const int* __restrict__ ei, int E) {
    int t = blockIdx.x * blockDim.x + threadIdx.x;
    int e = t >> 5;
    if (e >= E) return;
    int lane = t & 31;
    int dst = __ldg(ei + e);
    int src = __ldg(ei + E + e);
    float4 v = *(const float4*)(g_h + (size_t)src * H + lane * 4);
    red_add_v4(g_agg + (size_t)dst * KEXT + lane * 4, v);
}

// ---------------- tensor-core GEMM (tf32 hi/lo split, ~fp32 accuracy) --------
// C[M,N] = epi(A[M,K] @ B[K,N]); 128x128 block tile, 8 warps (2x4), 64x32/warp.
__global__ void __launch_bounds__(256, 1)
gemm_tc(const float* __restrict__ A, const float* __restrict__ B,
        float* __restrict__ C, int M, int N, int K,
        const float* __restrict__ scale, const float* __restrict__ shift, int relu) {
    __shared__ float As[2][16][132];
    __shared__ float Bs[2][16][132];
    int bm = blockIdx.x * 128, bn = blockIdx.y * 128;
    int tid = threadIdx.x;
    int wid = tid >> 5, lane = tid & 31;
    int gid = lane >> 2, tig = lane & 3;
    int wm = (wid >> 2) * 64, wn = (wid & 3) * 32;

    int arow = tid / 4, acol4 = (tid % 4) * 4;
    int brow = tid / 32, bcol4 = (tid % 32) * 4;

    float acc[4][4][4];
#pragma unroll
    for (int i = 0; i < 4; i++)
#pragma unroll
        for (int j = 0; j < 4; j++)
#pragma unroll
            for (int r = 0; r < 4; r++) acc[i][j][r] = 0.f;

    const float4 zero4 = make_float4(0.f, 0.f, 0.f, 0.f);
    float4 ra[2], rb[2];

    // prefetch + store chunk 0
    {
        int gr0 = bm + arow, gr1 = bm + arow + 64;
        ra[0] = (gr0 < M) ? *(const float4*)(A + (size_t)gr0 * K + acol4) : zero4;
        ra[1] = (gr1 < M) ? *(const float4*)(A + (size_t)gr1 * K + acol4) : zero4;
        rb[0] = *(const float4*)(B + (size_t)brow * N + bn + bcol4);
        rb[1] = *(const float4*)(B + (size_t)(brow + 8) * N + bn + bcol4);
        As[0][acol4 + 0][arow] = ra[0].x; As[0][acol4 + 1][arow] = ra[0].y;
        As[0][acol4 + 2][arow] = ra[0].z; As[0][acol4 + 3][arow] = ra[0].w;
        As[0][acol4 + 0][arow + 64] = ra[1].x; As[0][acol4 + 1][arow + 64] = ra[1].y;
        As[0][acol4 + 2][arow + 64] = ra[1].z; As[0][acol4 + 3][arow + 64] = ra[1].w;
        *(float4*)&Bs[0][brow][bcol4] = rb[0];
        *(float4*)&Bs[0][brow + 8][bcol4] = rb[1];
    }
    __syncthreads();

    int nch = K / 16;
    for (int c = 0; c < nch; c++) {
        int cur = c & 1;
        if (c + 1 < nch) {
            int k0 = (c + 1) * 16;
            int gr0 = bm + arow, gr1 = bm + arow + 64;
            ra[0] = (gr0 < M) ? *(const float4*)(A + (size_t)gr0 * K + k0 + acol4) : zero4;
            ra[1] = (gr1 < M) ? *(const float4*)(A + (size_t)gr1 * K + k0 + acol4) : zero4;
            rb[0] = *(const float4*)(B + (size_t)(k0 + brow) * N + bn + bcol4);
            rb[1] = *(const float4*)(B + (size_t)(k0 + brow + 8) * N + bn + bcol4);
        }
#pragma unroll
        for (int kb = 0; kb < 16; kb += 8) {
            uint32_t ahi[4][4], alo[4][4];
#pragma unroll
            for (int mi = 0; mi < 4; mi++) {
                int r = wm + mi * 16 + gid;
                float v0 = As[cur][kb + tig][r];
                float v1 = As[cur][kb + tig][r + 8];
                float v2 = As[cur][kb + tig + 4][r];
                float v3 = As[cur][kb + tig + 4][r + 8];
                split_tf32(v0, ahi[mi][0], alo[mi][0]);
                split_tf32(v1, ahi[mi][1], alo[mi][1]);
                split_tf32(v2, ahi[mi][2], alo[mi][2]);
                split_tf32(v3, ahi[mi][3], alo[mi][3]);
            }
            uint32_t bhi[4][2], blo[4][2];
#pragma unroll
            for (int ni = 0; ni < 4; ni++) {
                int cc = wn + ni * 8 + gid;
                float u0 = Bs[cur][kb + tig][cc];
                float u1 = Bs[cur][kb + tig + 4][cc];
                split_tf32(u0, bhi[ni][0], blo[ni][0]);
                split_tf32(u1, bhi[ni][1], blo[ni][1]);
            }
#pragma unroll
            for (int mi = 0; mi < 4; mi++)
#pragma unroll
                for (int ni = 0; ni < 4; ni++) {
                    mma_tf32(acc[mi][ni], ahi[mi], bhi[ni]);
                    mma_tf32(acc[mi][ni], alo[mi], bhi[ni]);
                    mma_tf32(acc[mi][ni], ahi[mi], blo[ni]);
                }
        }
        if (c + 1 < nch) {
            int nxt = 1 - cur;
            As[nxt][acol4 + 0][arow] = ra[0].x; As[nxt][acol4 + 1][arow] = ra[0].y;
            As[nxt][acol4 + 2][arow] = ra[0].z; As[nxt][acol4 + 3][arow] = ra[0].w;
            As[nxt][acol4 + 0][arow + 64] = ra[1].x; As[nxt][acol4 + 1][arow + 64] = ra[1].y;
            As[nxt][acol4 + 2][arow + 64] = ra[1].z; As[nxt][acol4 + 3][arow + 64] = ra[1].w;
            *(float4*)&Bs[nxt][brow][bcol4] = rb[0];
            *(float4*)&Bs[nxt][brow + 8][bcol4] = rb[1];
            __syncthreads();
        }
    }

    // epilogue
#pragma unroll
    for (int ni = 0; ni < 4; ni++) {
        int col = bn + wn + ni * 8 + tig * 2;
        float s0 = 1.f, s1 = 1.f, t0 = 0.f, t1 = 0.f;
        if (scale) { s0 = __ldg(scale + col); s1 = __ldg(scale + col + 1); }
        if (shift) { t0 = __ldg(shift + col); t1 = __ldg(shift + col + 1); }
#pragma unroll
        for (int mi = 0; mi < 4; mi++) {
            int r0 = bm + wm + mi * 16 + gid;
            float2 v0 = make_float2(acc[mi][ni][0] * s0 + t0, acc[mi][ni][1] * s1 + t1);
            float2 v1 = make_float2(acc[mi][ni][2] * s0 + t0, acc[mi][ni][3] * s1 + t1);
            if (relu) {
                v0.x = fmaxf(v0.x, 0.f); v0.y = fmaxf(v0.y, 0.f);
                v1.x = fmaxf(v1.x, 0.f); v1.y = fmaxf(v1.y, 0.f);
            }
            if (r0 < M)     *(float2*)(C + (size_t)r0 * N + col) = v0;
            if (r0 + 8 < M) *(float2*)(C + (size_t)(r0 + 8) * N + col) = v1;
        }
    }
}

// pool z1 (256-wide) by graph id
__global__ void pool_z(const int* __restrict__ batch, int N) {
    int t = blockIdx.x * blockDim.x + threadIdx.x;
    if (t >= N * 64) return;
    int n = t >> 6, j = t & 63;
    float4 v = *(const float4*)(g_z + (size_t)n * 256 + j * 4);
    int g = batch[n];
    red_add_v4(g_poolz + (size_t)g * 256 + j * 4, v);
}

// out[g][t] = (P[g] . wf[t]) / cnt_g + bf[t]
__global__ void pred2(float* __restrict__ out) {
    int g = blockIdx.x;
    int k = threadIdx.x;
    __shared__ float p[256];
    p[k] = g_poolz[g * 256 + k];
    __syncthreads();
    if (k < NT) {
        const float* wf = g_wf + k * 256;
        float s = 0.f;
#pragma unroll 16
        for (int i = 0; i < 256; i++) s += p[i] * wf[i];
        float cnt = fmaxf((float)g_cnt[g], 1.f);
        out[g * NT + k] = s / cnt + g_bf[k];
    }
}

// ---------------- launch -----------------------------------------------------
extern "C" void kernel_launch(void* const* d_in, const int* in_sizes, int n_in,
                              void* d_out, int out_size) {
    const int*   x        = (const int*)  d_in[0];
    const int*   ei       = (const int*)  d_in[1];
    const float* ea       = (const float*)d_in[2];
    const int*   batch    = (const int*)  d_in[3];
    const int*   sli      = (const int*)  d_in[4];
    const int*   slt      = (const int*)  d_in[5];
    const float* node_emb = (const float*)d_in[6];
    const float* L[2][10];
    for (int l = 0; l < 2; l++)
        for (int j = 0; j < 10; j++)
            L[l][j] = (const float*)d_in[7 + l * 10 + j];
    const float* pred_w = (const float*)d_in[27];
    const float* pred_b = (const float*)d_in[28];
    float* out = (float*)d_out;

    int N = in_sizes[0];
    int E = in_sizes[1] / 2;

    // Resolve DEVICE addresses of __device__ symbols (host shadow is ATS-readable
    // on GB300 -> silent garbage if passed directly).
    float *p_agg, *p_w1ext, *p_z, *p_h, *p_scale, *p_shift;
    cudaGetSymbolAddress((void**)&p_agg,   g_agg);
    cudaGetSymbolAddress((void**)&p_w1ext, g_w1ext);
    cudaGetSymbolAddress((void**)&p_z,     g_z);
    cudaGetSymbolAddress((void**)&p_h,     g_h);
    cudaGetSymbolAddress((void**)&p_scale, g_scale);
    cudaGetSymbolAddress((void**)&p_shift, g_shift);

    zero_kernel<<<(N * 9 + 255) / 256, 256>>>(N);
    init_h0<<<(N * 32 + 255) / 256, 256>>>(x, node_emb, batch, N);
    edge_presum<<<(E + 255) / 256, 256>>>(ei, ea, E);
    prep_pred<<<NT, 256>>>(L[1][8], L[1][9], pred_w, pred_b);

    for (int l = 0; l < 2; l++) {
        prep_layer<<<KEXT, 256>>>(L[l][0], L[l][1], L[l][2], L[l][3], L[l][4],
                                  L[l][5], L[l][6], L[l][7], sli, slt);
        agg_build<<<(N * 36 + 255) / 256, 256>>>(N);
        spmm<<<(E * 32 + 255) / 256, 256>>>(ei, E);
        // z = relu(bn(agg_ext @ w1_ext))   [N,144]x[144,256]
        gemm_tc<<<dim3((N + 127) / 128, 2), 256>>>(
            p_agg, p_w1ext, p_z, N, 256, KEXT, p_scale, p_shift, 1);
        if (l == 0) {
            // h1 = relu(z0 @ w2_0 + b2_0)   [N,256]x[256,128]
            gemm_tc<<<dim3((N + 127) / 128, 1), 256>>>(
                p_z, L[0][8], p_h, N, 128, 256, nullptr, L[0][9], 1);
        }
    }

    pool_z<<<(N * 64 + 255) / 256, 256>>>(batch, N);
    pred2<<<NG, 256>>>(out);
}

// round 5
// speedup vs baseline: 1.7878x; 1.1020x over previous
#include <cuda_runtime.h>
#include <math.h>
#include <stdint.h>

#define H 128
#define KEXT 144
#define EAP 12            // padded easum row: 9 attrs + deg + 2 pad
#define NG 256
#define NT 40
#define MAXN 50048
#define BN_EPS 1e-5f

// ---------------- scratch ----------------------------------------------------
__device__ float g_h[MAXN * H];
__device__ float g_agg[MAXN * KEXT];
__device__ float g_z[MAXN * 2 * H];
__device__ float g_easum[MAXN * EAP];
__device__ float g_w1ext[KEXT * 2 * H];
__device__ float g_scale[2 * H];
__device__ float g_shift[2 * H];
__device__ float g_poolz[NG * 2 * H];
__device__ float g_wf[NT * 2 * H];
__device__ float g_bf[NT];
__device__ int   g_cnt[NG];

// ---------------- helpers ---------------------------------------------------
__device__ __forceinline__ void red_add_v4(float* p, float4 v) {
    asm volatile("red.global.add.v4.f32 [%0], {%1,%2,%3,%4};"
                 :: "l"(p), "f"(v.x), "f"(v.y), "f"(v.z), "f"(v.w) : "memory");
}
__device__ __forceinline__ void red_add_v2(float* p, float2 v) {
    asm volatile("red.global.add.v2.f32 [%0], {%1,%2};"
                 :: "l"(p), "f"(v.x), "f"(v.y) : "memory");
}
__device__ __forceinline__ uint32_t f2tf32(float x) {
    uint32_t r; asm("cvt.rna.tf32.f32 %0, %1;" : "=r"(r) : "f"(x)); return r;
}
__device__ __forceinline__ void split_tf32(float v, uint32_t& hi, uint32_t& lo) {
    hi = f2tf32(v);
    lo = f2tf32(v - __uint_as_float(hi));
}
__device__ __forceinline__ void mma_tf32(float* d, const uint32_t* a, const uint32_t* b) {
    asm volatile("mma.sync.aligned.m16n8k8.row.col.f32.tf32.tf32.f32 "
                 "{%0,%1,%2,%3},{%4,%5,%6,%7},{%8,%9},{%0,%1,%2,%3};"
                 : "+f"(d[0]), "+f"(d[1]), "+f"(d[2]), "+f"(d[3])
                 : "r"(a[0]), "r"(a[1]), "r"(a[2]), "r"(a[3]),
                   "r"(b[0]), "r"(b[1]));
}

// ---------------- small kernels ----------------------------------------------
__global__ void zero_kernel(int N) {
    int i = blockIdx.x * blockDim.x + threadIdx.x;
    if (i < N * EAP)    g_easum[i] = 0.f;
    if (i < NG * 2 * H) g_poolz[i] = 0.f;
    if (i < NG)         g_cnt[i] = 0;
}

__global__ void init_h0(const int* __restrict__ x, const float* __restrict__ emb,
                        const int* __restrict__ batch, int N) {
    int t = blockIdx.x * blockDim.x + threadIdx.x;
    if (t >= N * 32) return;
    int n = t >> 5, j = t & 31;
    float4 v = *(const float4*)(emb + (size_t)x[n] * H + j * 4);
    *(float4*)(g_h + (size_t)n * H + j * 4) = v;
    if (j == 0) atomicAdd(&g_cnt[batch[n]], 1);
}

// 3 vector reductions per edge (attrs + deg folded as float)
__global__ void edge_presum(const int* __restrict__ ei, const float* __restrict__ ea, int E) {
    int e = blockIdx.x * blockDim.x + threadIdx.x;
    if (e >= E) return;
    int d = __ldg(ei + e);
    const float* a = ea + (size_t)e * 9;
    float4 v0 = make_float4(a[0], a[1], a[2], a[3]);
    float4 v1 = make_float4(a[4], a[5], a[6], a[7]);
    float4 v2 = make_float4(a[8], 1.f, 0.f, 0.f);
    float* s = g_easum + (size_t)d * EAP;
    red_add_v4(s, v0);
    red_add_v4(s + 4, v1);
    red_add_v4(s + 8, v2);
}

__global__ void prep_layer(const float* __restrict__ enc_w, const float* __restrict__ enc_b,
                           const float* __restrict__ w1,    const float* __restrict__ b1,
                           const float* __restrict__ gamma, const float* __restrict__ beta,
                           const float* __restrict__ mean,  const float* __restrict__ var,
                           const int* __restrict__ sli_p,   const int* __restrict__ slt_p) {
    int k = blockIdx.x;      // 0..143
    int c = threadIdx.x;     // 0..255
    if (k < 128) {
        g_w1ext[k * 256 + c] = w1[k * 256 + c];
    } else if (k < 139) {
        __shared__ float f[128];
        int j = k - 128;
        if (c < 128) {
            float fv;
            if (j < 9)       fv = enc_w[j * 128 + c];
            else if (j == 9) fv = enc_b[c];
            else             fv = (float)(*slt_p) * enc_w[(*sli_p) * 128 + c];
            f[c] = fv;
        }
        __syncthreads();
        float s = 0.f;
        const float* wb = w1 + 128 * 256 + c;
#pragma unroll 16
        for (int i = 0; i < 128; i++)
            s += f[i] * wb[i * 256];
        g_w1ext[k * 256 + c] = s;
    } else {
        g_w1ext[k * 256 + c] = 0.f;
    }
    if (k == 0) {
        float sc = gamma[c] * rsqrtf(var[c] + BN_EPS);
        g_scale[c] = sc;
        g_shift[c] = (b1[c] - mean[c]) * sc + beta[c];
    }
}

// g_wf[t][k] = sum_j w2[k][j]*(pw[j][t]+pw[j+128][t]); b fold parallel via smem
__global__ void prep_pred(const float* __restrict__ w2, const float* __restrict__ b2,
                          const float* __restrict__ pw, const float* __restrict__ pb) {
    int t = blockIdx.x;       // 0..39
    int k = threadIdx.x;      // 0..255
    __shared__ float pwsum[128];
    __shared__ float bprod[128];
    if (k < 128) {
        float pv = pw[k * NT + t] + pw[(k + 128) * NT + t];
        pwsum[k] = pv;
        bprod[k] = b2[k] * pv;
    }
    __syncthreads();
    float s = 0.f;
    const float* wr = w2 + (size_t)k * 128;
#pragma unroll 16
    for (int i = 0; i < 128; i++) s += wr[i] * pwsum[i];
    g_wf[t * 256 + k] = s;
    if (k == 0) {
        float bb = 0.f;
#pragma unroll 16
        for (int i = 0; i < 128; i++) bb += bprod[i];
        g_bf[t] = bb + pb[t];
    }
}

// agg rows: [h(self loop) | ea_sum | deg+1 | 1 | 0 pad]
__global__ void agg_build(int N) {
    int t = blockIdx.x * blockDim.x + threadIdx.x;
    if (t >= N * 36) return;
    int n = t / 36, q = t % 36;
    float4 v;
    if (q < 32) {
        v = *(const float4*)(g_h + (size_t)n * H + q * 4);
    } else if (q == 32) {
        v = *(const float4*)(g_easum + (size_t)n * EAP);
    } else if (q == 33) {
        v = *(const float4*)(g_easum + (size_t)n * EAP + 4);
    } else if (q == 34) {
        const float* s = g_easum + (size_t)n * EAP + 8;
        v = make_float4(s[0], s[1] + 1.f, 1.f, 0.f);   // s[1] = deg (float)
    } else {
        v = make_float4(0.f, 0.f, 0.f, 0.f);
    }
    *(float4*)(g_agg + (size_t)n * KEXT + q * 4) = v;
}

// 4 edges/warp, 8 lanes/edge; indices loaded once + shfl broadcast
__global__ void spmm(const int* __restrict__ ei, int E) {
    int t = blockIdx.x * blockDim.x + threadIdx.x;
    int warp = t >> 5;
    int lane = t & 31;
    int e0 = warp * 4;
    if (e0 >= E) return;
    int sub = lane >> 3, li = lane & 7;
    int eidx = e0 + (lane & 3);
    int v = 0;
    if (lane < 8 && eidx < E)
        v = (lane < 4) ? __ldg(ei + eidx) : __ldg(ei + E + eidx);
    int dst = __shfl_sync(0xffffffffu, v, sub);
    int src = __shfl_sync(0xffffffffu, v, sub + 4);
    if (e0 + sub >= E) return;
    const float* hp = g_h + (size_t)src * H;
    float* ap = g_agg + (size_t)dst * KEXT;
#pragma unroll
    for (int j = 0; j < 4; j++) {
        int off = j * 32 + li * 4;
        float4 x = *(const float4*)(hp + off);
        red_add_v4(ap + off, x);
    }
}

// ---------------- tensor-core GEMM (tf32 hi/lo split) ------------------------
// If batchmap != null: epilogue pools rows by graph id into pool (red.v2),
// nothing written to C.
__global__ void __launch_bounds__(256, 1)
gemm_tc(const float* __restrict__ A, const float* __restrict__ B,
        float* __restrict__ C, int M, int N, int K,
        const float* __restrict__ scale, const float* __restrict__ shift, int relu,
        const int* __restrict__ batchmap, float* __restrict__ pool) {
    __shared__ float As[2][16][132];
    __shared__ float Bs[2][16][132];
    int bm = blockIdx.x * 128, bn = blockIdx.y * 128;
    int tid = threadIdx.x;
    int wid = tid >> 5, lane = tid & 31;
    int gid = lane >> 2, tig = lane & 3;
    int wm = (wid >> 2) * 64, wn = (wid & 3) * 32;

    int arow = tid / 4, acol4 = (tid % 4) * 4;
    int brow = tid / 32, bcol4 = (tid % 32) * 4;

    float acc[4][4][4];
#pragma unroll
    for (int i = 0; i < 4; i++)
#pragma unroll
        for (int j = 0; j < 4; j++)
#pragma unroll
            for (int r = 0; r < 4; r++) acc[i][j][r] = 0.f;

    const float4 zero4 = make_float4(0.f, 0.f, 0.f, 0.f);
    float4 ra[2], rb[2];

    {
        int gr0 = bm + arow, gr1 = bm + arow + 64;
        ra[0] = (gr0 < M) ? *(const float4*)(A + (size_t)gr0 * K + acol4) : zero4;
        ra[1] = (gr1 < M) ? *(const float4*)(A + (size_t)gr1 * K + acol4) : zero4;
        rb[0] = *(const float4*)(B + (size_t)brow * N + bn + bcol4);
        rb[1] = *(const float4*)(B + (size_t)(brow + 8) * N + bn + bcol4);
        As[0][acol4 + 0][arow] = ra[0].x; As[0][acol4 + 1][arow] = ra[0].y;
        As[0][acol4 + 2][arow] = ra[0].z; As[0][acol4 + 3][arow] = ra[0].w;
        As[0][acol4 + 0][arow + 64] = ra[1].x; As[0][acol4 + 1][arow + 64] = ra[1].y;
        As[0][acol4 + 2][arow + 64] = ra[1].z; As[0][acol4 + 3][arow + 64] = ra[1].w;
        *(float4*)&Bs[0][brow][bcol4] = rb[0];
        *(float4*)&Bs[0][brow + 8][bcol4] = rb[1];
    }
    __syncthreads();

    int nch = K / 16;
    for (int c = 0; c < nch; c++) {
        int cur = c & 1;
        if (c + 1 < nch) {
            int k0 = (c + 1) * 16;
            int gr0 = bm + arow, gr1 = bm + arow + 64;
            ra[0] = (gr0 < M) ? *(const float4*)(A + (size_t)gr0 * K + k0 + acol4) : zero4;
            ra[1] = (gr1 < M) ? *(const float4*)(A + (size_t)gr1 * K + k0 + acol4) : zero4;
            rb[0] = *(const float4*)(B + (size_t)(k0 + brow) * N + bn + bcol4);
            rb[1] = *(const float4*)(B + (size_t)(k0 + brow + 8) * N + bn + bcol4);
        }
#pragma unroll
        for (int kb = 0; kb < 16; kb += 8) {
            uint32_t ahi[4][4], alo[4][4];
#pragma unroll
            for (int mi = 0; mi < 4; mi++) {
                int r = wm + mi * 16 + gid;
                split_tf32(As[cur][kb + tig][r],     ahi[mi][0], alo[mi][0]);
                split_tf32(As[cur][kb + tig][r + 8], ahi[mi][1], alo[mi][1]);
                split_tf32(As[cur][kb + tig + 4][r],     ahi[mi][2], alo[mi][2]);
                split_tf32(As[cur][kb + tig + 4][r + 8], ahi[mi][3], alo[mi][3]);
            }
            uint32_t bhi[4][2], blo[4][2];
#pragma unroll
            for (int ni = 0; ni < 4; ni++) {
                int cc = wn + ni * 8 + gid;
                split_tf32(Bs[cur][kb + tig][cc],     bhi[ni][0], blo[ni][0]);
                split_tf32(Bs[cur][kb + tig + 4][cc], bhi[ni][1], blo[ni][1]);
            }
#pragma unroll
            for (int mi = 0; mi < 4; mi++)
#pragma unroll
                for (int ni = 0; ni < 4; ni++) {
                    mma_tf32(acc[mi][ni], ahi[mi], bhi[ni]);
                    mma_tf32(acc[mi][ni], alo[mi], bhi[ni]);
                    mma_tf32(acc[mi][ni], ahi[mi], blo[ni]);
                }
        }
        if (c + 1 < nch) {
            int nxt = 1 - cur;
            As[nxt][acol4 + 0][arow] = ra[0].x; As[nxt][acol4 + 1][arow] = ra[0].y;
            As[nxt][acol4 + 2][arow] = ra[0].z; As[nxt][acol4 + 3][arow] = ra[0].w;
            As[nxt][acol4 + 0][arow + 64] = ra[1].x; As[nxt][acol4 + 1][arow + 64] = ra[1].y;
            As[nxt][acol4 + 2][arow + 64] = ra[1].z; As[nxt][acol4 + 3][arow + 64] = ra[1].w;
            *(float4*)&Bs[nxt][brow][bcol4] = rb[0];
            *(float4*)&Bs[nxt][brow + 8][bcol4] = rb[1];
            __syncthreads();
        }
    }

#pragma unroll
    for (int ni = 0; ni < 4; ni++) {
        int col = bn + wn + ni * 8 + tig * 2;
        float s0 = 1.f, s1 = 1.f, t0 = 0.f, t1 = 0.f;
        if (scale) { s0 = __ldg(scale + col); s1 = __ldg(scale + col + 1); }
        if (shift) { t0 = __ldg(shift + col); t1 = __ldg(shift + col + 1); }
#pragma unroll
        for (int mi = 0; mi < 4; mi++) {
            int r0 = bm + wm + mi * 16 + gid;
            float2 v0 = make_float2(acc[mi][ni][0] * s0 + t0, acc[mi][ni][1] * s1 + t1);
            float2 v1 = make_float2(acc[mi][ni][2] * s0 + t0, acc[mi][ni][3] * s1 + t1);
            if (relu) {
                v0.x = fmaxf(v0.x, 0.f); v0.y = fmaxf(v0.y, 0.f);
                v1.x = fmaxf(v1.x, 0.f); v1.y = fmaxf(v1.y, 0.f);
            }
            if (batchmap) {
                if (r0 < M) {
                    int g = __ldg(batchmap + r0);
                    red_add_v2(pool + (size_t)g * 256 + col, v0);
                }
                if (r0 + 8 < M) {
                    int g = __ldg(batchmap + r0 + 8);
                    red_add_v2(pool + (size_t)g * 256 + col, v1);
                }
            } else {
                if (r0 < M)     *(float2*)(C + (size_t)r0 * N + col) = v0;
                if (r0 + 8 < M) *(float2*)(C + (size_t)(r0 + 8) * N + col) = v1;
            }
        }
    }
}

// out[g][t] = (P[g] . wf[t]) / cnt_g + bf[t]
__global__ void pred2(float* __restrict__ out) {
    int g = blockIdx.x;
    int k = threadIdx.x;
    __shared__ float p[256];
    p[k] = g_poolz[g * 256 + k];
    __syncthreads();
    if (k < NT) {
        const float* wf = g_wf + k * 256;
        float s = 0.f;
#pragma unroll 16
        for (int i = 0; i < 256; i++) s += p[i] * wf[i];
        float cnt = fmaxf((float)g_cnt[g], 1.f);
        out[g * NT + k] = s / cnt + g_bf[k];
    }
}

// ---------------- launch -----------------------------------------------------
extern "C" void kernel_launch(void* const* d_in, const int* in_sizes, int n_in,
                              void* d_out, int out_size) {
    const int*   x        = (const int*)  d_in[0];
    const int*   ei       = (const int*)  d_in[1];
    const float* ea       = (const float*)d_in[2];
    const int*   batch    = (const int*)  d_in[3];
    const int*   sli      = (const int*)  d_in[4];
    const int*   slt      = (const int*)  d_in[5];
    const float* node_emb = (const float*)d_in[6];
    const float* L[2][10];
    for (int l = 0; l < 2; l++)
        for (int j = 0; j < 10; j++)
            L[l][j] = (const float*)d_in[7 + l * 10 + j];
    const float* pred_w = (const float*)d_in[27];
    const float* pred_b = (const float*)d_in[28];
    float* out = (float*)d_out;

    int N = in_sizes[0];
    int E = in_sizes[1] / 2;

    float *p_agg, *p_w1ext, *p_z, *p_h, *p_scale, *p_shift, *p_poolz;
    cudaGetSymbolAddress((void**)&p_agg,   g_agg);
    cudaGetSymbolAddress((void**)&p_w1ext, g_w1ext);
    cudaGetSymbolAddress((void**)&p_z,     g_z);
    cudaGetSymbolAddress((void**)&p_h,     g_h);
    cudaGetSymbolAddress((void**)&p_scale, g_scale);
    cudaGetSymbolAddress((void**)&p_shift, g_shift);
    cudaGetSymbolAddress((void**)&p_poolz, g_poolz);

    zero_kernel<<<(N * EAP + 255) / 256, 256>>>(N);
    init_h0<<<(N * 32 + 255) / 256, 256>>>(x, node_emb, batch, N);
    edge_presum<<<(E + 255) / 256, 256>>>(ei, ea, E);
    prep_pred<<<NT, 256>>>(L[1][8], L[1][9], pred_w, pred_b);

    int spmm_threads = ((E + 3) / 4) * 32;
    for (int l = 0; l < 2; l++) {
        prep_layer<<<KEXT, 256>>>(L[l][0], L[l][1], L[l][2], L[l][3], L[l][4],
                                  L[l][5], L[l][6], L[l][7], sli, slt);
        agg_build<<<(N * 36 + 255) / 256, 256>>>(N);
        spmm<<<(spmm_threads + 255) / 256, 256>>>(ei, E);
        if (l == 0) {
            gemm_tc<<<dim3((N + 127) / 128, 2), 256>>>(
                p_agg, p_w1ext, p_z, N, 256, KEXT, p_scale, p_shift, 1, nullptr, nullptr);
            gemm_tc<<<dim3((N + 127) / 128, 1), 256>>>(
                p_z, L[0][8], p_h, N, 128, 256, nullptr, L[0][9], 1, nullptr, nullptr);
        } else {
            // z1 = relu(bn(agg @ w1ext)) pooled directly by graph id
            gemm_tc<<<dim3((N + 127) / 128, 2), 256>>>(
                p_agg, p_w1ext, p_z, N, 256, KEXT, p_scale, p_shift, 1, batch, p_poolz);
        }
    }

    pred2<<<NG, 256>>>(out);
}

// round 6
// speedup vs baseline: 2.2194x; 1.2414x over previous
#include <cuda_runtime.h>
#include <math.h>
#include <stdint.h>

#define H 128
#define KEXT 144
#define EAP 12
#define NG 256
#define NT 40
#define MAXN 50048
#define BN_EPS 1e-5f
#define APAD 132
#define BPAD 136

// ---------------- scratch ----------------------------------------------------
__device__ float g_h[MAXN * H];
__device__ float g_agg[MAXN * KEXT];
__device__ float g_z[MAXN * 2 * H];
__device__ float g_easum[MAXN * EAP];
__device__ float g_w1ext[KEXT * 2 * H];
__device__ float g_scale[2 * H];
__device__ float g_shift[2 * H];
__device__ float g_poolz[NG * 2 * H];
__device__ float g_wf[NT * 2 * H];
__device__ float g_bf[NT];
__device__ int   g_cnt[NG];

// ---------------- helpers ---------------------------------------------------
__device__ __forceinline__ void red_add_v4(float* p, float4 v) {
    asm volatile("red.global.add.v4.f32 [%0], {%1,%2,%3,%4};"
                 :: "l"(p), "f"(v.x), "f"(v.y), "f"(v.z), "f"(v.w) : "memory");
}
__device__ __forceinline__ void red_add_v2(float* p, float2 v) {
    asm volatile("red.global.add.v2.f32 [%0], {%1,%2};"
                 :: "l"(p), "f"(v.x), "f"(v.y) : "memory");
}
// pack two floats into bf16x2: lo -> bits[15:0], hi -> bits[31:16]
__device__ __forceinline__ uint32_t pack2(float lo, float hi) {
    uint32_t r;
    asm("cvt.rn.bf16x2.f32 %0, %1, %2;" : "=r"(r) : "f"(hi), "f"(lo));
    return r;
}
// split (f0,f1) pair into bf16x2 hi plane + bf16x2 residual plane
__device__ __forceinline__ void split2(float f0, float f1, uint32_t& hi, uint32_t& lo) {
    hi = pack2(f0, f1);
    float h0 = __uint_as_float(hi << 16);
    float h1 = __uint_as_float(hi & 0xffff0000u);
    lo = pack2(f0 - h0, f1 - h1);
}
__device__ __forceinline__ void mma_bf16(float* d, const uint32_t* a, const uint32_t* b) {
    asm volatile("mma.sync.aligned.m16n8k16.row.col.f32.bf16.bf16.f32 "
                 "{%0,%1,%2,%3},{%4,%5,%6,%7},{%8,%9},{%0,%1,%2,%3};"
                 : "+f"(d[0]), "+f"(d[1]), "+f"(d[2]), "+f"(d[3])
                 : "r"(a[0]), "r"(a[1]), "r"(a[2]), "r"(a[3]),
                   "r"(b[0]), "r"(b[1]));
}

// ---------------- small kernels ----------------------------------------------
__global__ void zero_kernel(int N) {
    int i = blockIdx.x * blockDim.x + threadIdx.x;
    if (i < N * EAP)    g_easum[i] = 0.f;
    if (i < NG * 2 * H) g_poolz[i] = 0.f;
    if (i < NG)         g_cnt[i] = 0;
}

__global__ void init_h0(const int* __restrict__ x, const float* __restrict__ emb,
                        const int* __restrict__ batch, int N) {
    int t = blockIdx.x * blockDim.x + threadIdx.x;
    if (t >= N * 32) return;
    int n = t >> 5, j = t & 31;
    float4 v = *(const float4*)(emb + (size_t)x[n] * H + j * 4);
    *(float4*)(g_h + (size_t)n * H + j * 4) = v;
    if (j == 0) atomicAdd(&g_cnt[batch[n]], 1);
}

__global__ void edge_presum(const int* __restrict__ ei, const float* __restrict__ ea, int E) {
    int e = blockIdx.x * blockDim.x + threadIdx.x;
    if (e >= E) return;
    int d = __ldg(ei + e);
    const float* a = ea + (size_t)e * 9;
    float4 v0 = make_float4(a[0], a[1], a[2], a[3]);
    float4 v1 = make_float4(a[4], a[5], a[6], a[7]);
    float4 v2 = make_float4(a[8], 1.f, 0.f, 0.f);
    float* s = g_easum + (size_t)d * EAP;
    red_add_v4(s, v0);
    red_add_v4(s + 4, v1);
    red_add_v4(s + 8, v2);
}

__global__ void prep_layer(const float* __restrict__ enc_w, const float* __restrict__ enc_b,
                           const float* __restrict__ w1,    const float* __restrict__ b1,
                           const float* __restrict__ gamma, const float* __restrict__ beta,
                           const float* __restrict__ mean,  const float* __restrict__ var,
                           const int* __restrict__ sli_p,   const int* __restrict__ slt_p) {
    int k = blockIdx.x;      // 0..143
    int c = threadIdx.x;     // 0..255
    if (k < 128) {
        g_w1ext[k * 256 + c] = w1[k * 256 + c];
    } else if (k < 139) {
        __shared__ float f[128];
        int j = k - 128;
        if (c < 128) {
            float fv;
            if (j < 9)       fv = enc_w[j * 128 + c];
            else if (j == 9) fv = enc_b[c];
            else             fv = (float)(*slt_p) * enc_w[(*sli_p) * 128 + c];
            f[c] = fv;
        }
        __syncthreads();
        float s = 0.f;
        const float* wb = w1 + 128 * 256 + c;
#pragma unroll 16
        for (int i = 0; i < 128; i++)
            s += f[i] * wb[i * 256];
        g_w1ext[k * 256 + c] = s;
    } else {
        g_w1ext[k * 256 + c] = 0.f;
    }
    if (k == 0) {
        float sc = gamma[c] * rsqrtf(var[c] + BN_EPS);
        g_scale[c] = sc;
        g_shift[c] = (b1[c] - mean[c]) * sc + beta[c];
    }
}

// One block per output column k (coalesced w2 row into smem), 40 threads dot
// against pw with t-consecutive (coalesced) loads. Block 256 computes g_bf.
__global__ void prep_pred(const float* __restrict__ w2, const float* __restrict__ b2,
                          const float* __restrict__ pw, const float* __restrict__ pb) {
    int k = blockIdx.x;
    __shared__ float row[128];
    int i = threadIdx.x;
    if (k < 256) {
        row[i] = w2[k * 128 + i];
        __syncthreads();
        if (i < NT) {
            float s = 0.f;
#pragma unroll 8
            for (int j = 0; j < 128; j++)
                s += row[j] * (__ldg(pw + j * NT + i) + __ldg(pw + (j + 128) * NT + i));
            g_wf[i * 256 + k] = s;
        }
    } else {
        row[i] = b2[i];
        __syncthreads();
        if (i < NT) {
            float s = 0.f;
#pragma unroll 8
            for (int j = 0; j < 128; j++)
                s += row[j] * (__ldg(pw + j * NT + i) + __ldg(pw + (j + 128) * NT + i));
            g_bf[i] = s + pb[i];
        }
    }
}

__global__ void agg_build(int N) {
    int t = blockIdx.x * blockDim.x + threadIdx.x;
    if (t >= N * 36) return;
    int n = t / 36, q = t % 36;
    float4 v;
    if (q < 32) {
        v = *(const float4*)(g_h + (size_t)n * H + q * 4);
    } else if (q == 32) {
        v = *(const float4*)(g_easum + (size_t)n * EAP);
    } else if (q == 33) {
        v = *(const float4*)(g_easum + (size_t)n * EAP + 4);
    } else if (q == 34) {
        const float* s = g_easum + (size_t)n * EAP + 8;
        v = make_float4(s[0], s[1] + 1.f, 1.f, 0.f);
    } else {
        v = make_float4(0.f, 0.f, 0.f, 0.f);
    }
    *(float4*)(g_agg + (size_t)n * KEXT + q * 4) = v;
}

// 4 edges/warp, 8 lanes/edge; indices loaded once + shfl broadcast
__global__ void spmm(const int* __restrict__ ei, int E) {
    int t = blockIdx.x * blockDim.x + threadIdx.x;
    int warp = t >> 5;
    int lane = t & 31;
    int e0 = warp * 4;
    if (e0 >= E) return;
    int sub = lane >> 3, li = lane & 7;
    int eidx = e0 + (lane & 3);
    int v = 0;
    if (lane < 8 && eidx < E)
        v = (lane < 4) ? __ldg(ei + eidx) : __ldg(ei + E + eidx);
    int dst = __shfl_sync(0xffffffffu, v, sub);
    int src = __shfl_sync(0xffffffffu, v, sub + 4);
    if (e0 + sub >= E) return;
    const float* hp = g_h + (size_t)src * H;
    float* ap = g_agg + (size_t)dst * KEXT;
#pragma unroll
    for (int j = 0; j < 4; j++) {
        int off = j * 32 + li * 4;
        float4 x = *(const float4*)(hp + off);
        red_add_v4(ap + off, x);
    }
}

// ---------------- tensor-core GEMM (bf16 hi/lo split, fp32 accumulate) --------
// Producer converts fp32 -> packed bf16x2 hi/lo planes once; consumer is pure
// LDS + m16n8k16 MMA (3 MMAs: hh, lh, hl).
__global__ void __launch_bounds__(256, 1)
gemm_tc(const float* __restrict__ A, const float* __restrict__ B,
        float* __restrict__ C, int M, int N, int K,
        const float* __restrict__ scale, const float* __restrict__ shift, int relu,
        const int* __restrict__ batchmap, float* __restrict__ pool) {
    __shared__ uint32_t Ah[2][8][APAD], Al[2][8][APAD];
    __shared__ uint32_t Bh[2][8][BPAD], Bl[2][8][BPAD];
    int bm = blockIdx.x * 128, bn = blockIdx.y * 128;
    int tid = threadIdx.x;
    int wid = tid >> 5, lane = tid & 31;
    int gid = lane >> 2, tig = lane & 3;
    int wm = (wid >> 2) * 64, wn = (wid & 3) * 32;

    int arow = tid >> 2, aq = tid & 3;          // A: rows arow, arow+64; k = aq*4..aq*4+3
    int bkp = tid >> 5, bc4 = (tid & 31) * 4;   // B: k-pair bkp (rows 2bkp,2bkp+1), cols bc4..+3

    float acc[4][4][4];
#pragma unroll
    for (int i = 0; i < 4; i++)
#pragma unroll
        for (int j = 0; j < 4; j++)
#pragma unroll
            for (int r = 0; r < 4; r++) acc[i][j][r] = 0.f;

    const float4 zero4 = make_float4(0.f, 0.f, 0.f, 0.f);
    float4 ra[2], rb[2];

    auto store_tiles = [&](int buf) {
#pragma unroll
        for (int i = 0; i < 2; i++) {
            uint32_t h0, l0, h1, l1;
            split2(ra[i].x, ra[i].y, h0, l0);
            split2(ra[i].z, ra[i].w, h1, l1);
            int r = arow + i * 64;
            Ah[buf][aq * 2][r] = h0;     Al[buf][aq * 2][r] = l0;
            Ah[buf][aq * 2 + 1][r] = h1; Al[buf][aq * 2 + 1][r] = l1;
        }
        uint32_t h[4], l[4];
        split2(rb[0].x, rb[1].x, h[0], l[0]);
        split2(rb[0].y, rb[1].y, h[1], l[1]);
        split2(rb[0].z, rb[1].z, h[2], l[2]);
        split2(rb[0].w, rb[1].w, h[3], l[3]);
        *(uint4*)&Bh[buf][bkp][bc4] = make_uint4(h[0], h[1], h[2], h[3]);
        *(uint4*)&Bl[buf][bkp][bc4] = make_uint4(l[0], l[1], l[2], l[3]);
    };

    // prefetch chunk 0
    {
        int gr0 = bm + arow, gr1 = bm + arow + 64;
        ra[0] = (gr0 < M) ? *(const float4*)(A + (size_t)gr0 * K + aq * 4) : zero4;
        ra[1] = (gr1 < M) ? *(const float4*)(A + (size_t)gr1 * K + aq * 4) : zero4;
        rb[0] = *(const float4*)(B + (size_t)(2 * bkp) * N + bn + bc4);
        rb[1] = *(const float4*)(B + (size_t)(2 * bkp + 1) * N + bn + bc4);
        store_tiles(0);
    }
    __syncthreads();

    int nch = K / 16;
    for (int c = 0; c < nch; c++) {
        int cur = c & 1;
        if (c + 1 < nch) {
            int k0 = (c + 1) * 16;
            int gr0 = bm + arow, gr1 = bm + arow + 64;
            ra[0] = (gr0 < M) ? *(const float4*)(A + (size_t)gr0 * K + k0 + aq * 4) : zero4;
            ra[1] = (gr1 < M) ? *(const float4*)(A + (size_t)gr1 * K + k0 + aq * 4) : zero4;
            rb[0] = *(const float4*)(B + (size_t)(k0 + 2 * bkp) * N + bn + bc4);
            rb[1] = *(const float4*)(B + (size_t)(k0 + 2 * bkp + 1) * N + bn + bc4);
        }
        {
            uint32_t ahi[4][4], alo[4][4];
#pragma unroll
            for (int mi = 0; mi < 4; mi++) {
                int r = wm + mi * 16 + gid;
                ahi[mi][0] = Ah[cur][tig][r];     alo[mi][0] = Al[cur][tig][r];
                ahi[mi][1] = Ah[cur][tig][r + 8]; alo[mi][1] = Al[cur][tig][r + 8];
                ahi[mi][2] = Ah[cur][tig + 4][r];     alo[mi][2] = Al[cur][tig + 4][r];
                ahi[mi][3] = Ah[cur][tig + 4][r + 8]; alo[mi][3] = Al[cur][tig + 4][r + 8];
            }
            uint32_t bhi[4][2], blo[4][2];
#pragma unroll
            for (int ni = 0; ni < 4; ni++) {
                int cc = wn + ni * 8 + gid;
                bhi[ni][0] = Bh[cur][tig][cc];     blo[ni][0] = Bl[cur][tig][cc];
                bhi[ni][1] = Bh[cur][tig + 4][cc]; blo[ni][1] = Bl[cur][tig + 4][cc];
            }
#pragma unroll
            for (int mi = 0; mi < 4; mi++)
#pragma unroll
                for (int ni = 0; ni < 4; ni++) {
                    mma_bf16(acc[mi][ni], ahi[mi], bhi[ni]);
                    mma_bf16(acc[mi][ni], alo[mi], bhi[ni]);
                    mma_bf16(acc[mi][ni], ahi[mi], blo[ni]);
                }
        }
        if (c + 1 < nch) {
            __syncthreads();
            store_tiles(1 - cur);
            __syncthreads();
        }
    }

#pragma unroll
    for (int ni = 0; ni < 4; ni++) {
        int col = bn + wn + ni * 8 + tig * 2;
        float s0 = 1.f, s1 = 1.f, t0 = 0.f, t1 = 0.f;
        if (scale) { s0 = __ldg(scale + col); s1 = __ldg(scale + col + 1); }
        if (shift) { t0 = __ldg(shift + col); t1 = __ldg(shift + col + 1); }
#pragma unroll
        for (int mi = 0; mi < 4; mi++) {
            int r0 = bm + wm + mi * 16 + gid;
            float2 v0 = make_float2(acc[mi][ni][0] * s0 + t0, acc[mi][ni][1] * s1 + t1);
            float2 v1 = make_float2(acc[mi][ni][2] * s0 + t0, acc[mi][ni][3] * s1 + t1);
            if (relu) {
                v0.x = fmaxf(v0.x, 0.f); v0.y = fmaxf(v0.y, 0.f);
                v1.x = fmaxf(v1.x, 0.f); v1.y = fmaxf(v1.y, 0.f);
            }
            if (batchmap) {
                if (r0 < M) {
                    int g = __ldg(batchmap + r0);
                    red_add_v2(pool + (size_t)g * 256 + col, v0);
                }
                if (r0 + 8 < M) {
                    int g = __ldg(batchmap + r0 + 8);
                    red_add_v2(pool + (size_t)g * 256 + col, v1);
                }
            } else {
                if (r0 < M)     *(float2*)(C + (size_t)r0 * N + col) = v0;
                if (r0 + 8 < M) *(float2*)(C + (size_t)(r0 + 8) * N + col) = v1;
            }
        }
    }
}

// out[g][t] = (P[g] . wf[t]) / cnt_g + bf[t]
__global__ void pred2(float* __restrict__ out) {
    int g = blockIdx.x;
    int k = threadIdx.x;
    __shared__ float p[256];
    p[k] = g_poolz[g * 256 + k];
    __syncthreads();
    if (k < NT) {
        const float* wf = g_wf + k * 256;
        float s = 0.f;
#pragma unroll 16
        for (int i = 0; i < 256; i++) s += p[i] * wf[i];
        float cnt = fmaxf((float)g_cnt[g], 1.f);
        out[g * NT + k] = s / cnt + g_bf[k];
    }
}

// ---------------- launch -----------------------------------------------------
extern "C" void kernel_launch(void* const* d_in, const int* in_sizes, int n_in,
                              void* d_out, int out_size) {
    const int*   x        = (const int*)  d_in[0];
    const int*   ei       = (const int*)  d_in[1];
    const float* ea       = (const float*)d_in[2];
    const int*   batch    = (const int*)  d_in[3];
    const int*   sli      = (const int*)  d_in[4];
    const int*   slt      = (const int*)  d_in[5];
    const float* node_emb = (const float*)d_in[6];
    const float* L[2][10];
    for (int l = 0; l < 2; l++)
        for (int j = 0; j < 10; j++)
            L[l][j] = (const float*)d_in[7 + l * 10 + j];
    const float* pred_w = (const float*)d_in[27];
    const float* pred_b = (const float*)d_in[28];
    float* out = (float*)d_out;

    int N = in_sizes[0];
    int E = in_sizes[1] / 2;

    float *p_agg, *p_w1ext, *p_z, *p_h, *p_scale, *p_shift, *p_poolz;
    cudaGetSymbolAddress((void**)&p_agg,   g_agg);
    cudaGetSymbolAddress((void**)&p_w1ext, g_w1ext);
    cudaGetSymbolAddress((void**)&p_z,     g_z);
    cudaGetSymbolAddress((void**)&p_h,     g_h);
    cudaGetSymbolAddress((void**)&p_scale, g_scale);
    cudaGetSymbolAddress((void**)&p_shift, g_shift);
    cudaGetSymbolAddress((void**)&p_poolz, g_poolz);

    zero_kernel<<<(N * EAP + 255) / 256, 256>>>(N);
    init_h0<<<(N * 32 + 255) / 256, 256>>>(x, node_emb, batch, N);
    edge_presum<<<(E + 255) / 256, 256>>>(ei, ea, E);
    prep_pred<<<NG + 1, 128>>>(L[1][8], L[1][9], pred_w, pred_b);

    int spmm_threads = ((E + 3) / 4) * 32;
    for (int l = 0; l < 2; l++) {
        prep_layer<<<KEXT, 256>>>(L[l][0], L[l][1], L[l][2], L[l][3], L[l][4],
                                  L[l][5], L[l][6], L[l][7], sli, slt);
        agg_build<<<(N * 36 + 255) / 256, 256>>>(N);
        spmm<<<(spmm_threads + 255) / 256, 256>>>(ei, E);
        if (l == 0) {
            gemm_tc<<<dim3((N + 127) / 128, 2), 256>>>(
                p_agg, p_w1ext, p_z, N, 256, KEXT, p_scale, p_shift, 1, nullptr, nullptr);
            gemm_tc<<<dim3((N + 127) / 128, 1), 256>>>(
                p_z, L[0][8], p_h, N, 128, 256, nullptr, L[0][9], 1, nullptr, nullptr);
        } else {
            gemm_tc<<<dim3((N + 127) / 128, 2), 256>>>(
                p_agg, p_w1ext, p_z, N, 256, KEXT, p_scale, p_shift, 1, batch, p_poolz);
        }
    }

    pred2<<<NG, 256>>>(out);
}

// round 7
// speedup vs baseline: 2.5575x; 1.1523x over previous
#include <cuda_runtime.h>
#include <math.h>
#include <stdint.h>

#define H 128
#define KEXT 144
#define EAP 12
#define NG 256
#define NT 40
#define MAXN 50048
#define MAXE 600064
#define BN_EPS 1e-5f
#define APAD 132
#define BPAD 136

// ---------------- scratch ----------------------------------------------------
__device__ float g_h[MAXN * H];
__device__ float g_agg[MAXN * KEXT];
__device__ float g_z[MAXN * 2 * H];
__device__ float g_easum[MAXN * EAP];
__device__ float g_w1ext[KEXT * 2 * H];
__device__ float g_scale[2 * H];
__device__ float g_shift[2 * H];
__device__ float g_poolz[NG * 2 * H];
__device__ float g_wf[NT * 2 * H];
__device__ float g_bf[NT];
__device__ int   g_cnt[NG];
__device__ int   g_off[MAXN + 1];
__device__ int   g_bsum[256];
__device__ int   g_fill[MAXN];
__device__ int   g_csrc[MAXE];

// ---------------- helpers ---------------------------------------------------
__device__ __forceinline__ void red_add_v4(float* p, float4 v) {
    asm volatile("red.global.add.v4.f32 [%0], {%1,%2,%3,%4};"
                 :: "l"(p), "f"(v.x), "f"(v.y), "f"(v.z), "f"(v.w) : "memory");
}
__device__ __forceinline__ void red_add_v2(float* p, float2 v) {
    asm volatile("red.global.add.v2.f32 [%0], {%1,%2};"
                 :: "l"(p), "f"(v.x), "f"(v.y) : "memory");
}
__device__ __forceinline__ uint32_t pack2(float lo, float hi) {
    uint32_t r;
    asm("cvt.rn.bf16x2.f32 %0, %1, %2;" : "=r"(r) : "f"(hi), "f"(lo));
    return r;
}
__device__ __forceinline__ void split2(float f0, float f1, uint32_t& hi, uint32_t& lo) {
    hi = pack2(f0, f1);
    float h0 = __uint_as_float(hi << 16);
    float h1 = __uint_as_float(hi & 0xffff0000u);
    lo = pack2(f0 - h0, f1 - h1);
}
__device__ __forceinline__ void mma_bf16(float* d, const uint32_t* a, const uint32_t* b) {
    asm volatile("mma.sync.aligned.m16n8k16.row.col.f32.bf16.bf16.f32 "
                 "{%0,%1,%2,%3},{%4,%5,%6,%7},{%8,%9},{%0,%1,%2,%3};"
                 : "+f"(d[0]), "+f"(d[1]), "+f"(d[2]), "+f"(d[3])
                 : "r"(a[0]), "r"(a[1]), "r"(a[2]), "r"(a[3]),
                   "r"(b[0]), "r"(b[1]));
}

// ---------------- small kernels ----------------------------------------------
__global__ void zero_kernel(int N) {
    int i = blockIdx.x * blockDim.x + threadIdx.x;
    if (i < N * EAP)    g_easum[i] = 0.f;
    if (i < NG * 2 * H) g_poolz[i] = 0.f;
    if (i < NG)         g_cnt[i] = 0;
    if (i < N)          g_fill[i] = 0;
}

__global__ void init_h0(const int* __restrict__ x, const float* __restrict__ emb,
                        const int* __restrict__ batch, int N) {
    int t = blockIdx.x * blockDim.x + threadIdx.x;
    if (t >= N * 32) return;
    int n = t >> 5, j = t & 31;
    float4 v = *(const float4*)(emb + (size_t)x[n] * H + j * 4);
    *(float4*)(g_h + (size_t)n * H + j * 4) = v;
    if (j == 0) atomicAdd(&g_cnt[batch[n]], 1);
}

__global__ void edge_presum(const int* __restrict__ ei, const float* __restrict__ ea, int E) {
    int e = blockIdx.x * blockDim.x + threadIdx.x;
    if (e >= E) return;
    int d = __ldg(ei + e);
    const float* a = ea + (size_t)e * 9;
    float4 v0 = make_float4(a[0], a[1], a[2], a[3]);
    float4 v1 = make_float4(a[4], a[5], a[6], a[7]);
    float4 v2 = make_float4(a[8], 1.f, 0.f, 0.f);
    float* s = g_easum + (size_t)d * EAP;
    red_add_v4(s, v0);
    red_add_v4(s + 4, v1);
    red_add_v4(s + 8, v2);
}

// ---- CSR build: 3-phase exclusive scan of deg, then slot scatter ------------
__global__ void scan1(int N) {
    int b = blockIdx.x, t = threadIdx.x;
    int i = b * 256 + t;
    int v = (i < N) ? (int)g_easum[(size_t)i * EAP + 9] : 0;
    __shared__ int sm[256];
    sm[t] = v;
    __syncthreads();
#pragma unroll
    for (int off = 1; off < 256; off <<= 1) {
        int x = (t >= off) ? sm[t - off] : 0;
        __syncthreads();
        sm[t] += x;
        __syncthreads();
    }
    if (i < N) g_off[i] = sm[t] - v;      // exclusive within block
    if (t == 255) g_bsum[b] = sm[255];
}
__global__ void scan2(int B) {
    int t = threadIdx.x;
    int v = (t < B) ? g_bsum[t] : 0;
    __shared__ int sm[256];
    sm[t] = v;
    __syncthreads();
#pragma unroll
    for (int off = 1; off < 256; off <<= 1) {
        int x = (t >= off) ? sm[t - off] : 0;
        __syncthreads();
        sm[t] += x;
        __syncthreads();
    }
    if (t < B) g_bsum[t] = sm[t] - v;     // exclusive
}
__global__ void scan3(int N, int E) {
    int i = blockIdx.x * blockDim.x + threadIdx.x;
    if (i < N) g_off[i] += g_bsum[i >> 8];
    if (i == 0) g_off[N] = E;
}
__global__ void scatter(const int* __restrict__ ei, int E) {
    int e = blockIdx.x * blockDim.x + threadIdx.x;
    if (e >= E) return;
    int d = __ldg(ei + e);
    int slot = atomicAdd(&g_fill[d], 1);
    g_csrc[g_off[d] + slot] = __ldg(ei + E + e);
}

// ---- fused neighbor gather + agg row build (warp per node) ------------------
__global__ void aggregate(int N) {
    int t = blockIdx.x * blockDim.x + threadIdx.x;
    int n = t >> 5;
    if (n >= N) return;
    int lane = t & 31;
    float4 acc = *(const float4*)(g_h + (size_t)n * H + lane * 4);  // self loop
    int beg = g_off[n], end = g_off[n + 1];
    int e = beg;
    for (; e + 4 <= end; e += 4) {
        int s0 = __ldg(g_csrc + e),     s1 = __ldg(g_csrc + e + 1);
        int s2 = __ldg(g_csrc + e + 2), s3 = __ldg(g_csrc + e + 3);
        float4 v0 = *(const float4*)(g_h + (size_t)s0 * H + lane * 4);
        float4 v1 = *(const float4*)(g_h + (size_t)s1 * H + lane * 4);
        float4 v2 = *(const float4*)(g_h + (size_t)s2 * H + lane * 4);
        float4 v3 = *(const float4*)(g_h + (size_t)s3 * H + lane * 4);
        acc.x += v0.x + v1.x + v2.x + v3.x;
        acc.y += v0.y + v1.y + v2.y + v3.y;
        acc.z += v0.z + v1.z + v2.z + v3.z;
        acc.w += v0.w + v1.w + v2.w + v3.w;
    }
    for (; e < end; e++) {
        int s0 = __ldg(g_csrc + e);
        float4 v0 = *(const float4*)(g_h + (size_t)s0 * H + lane * 4);
        acc.x += v0.x; acc.y += v0.y; acc.z += v0.z; acc.w += v0.w;
    }
    *(float4*)(g_agg + (size_t)n * KEXT + lane * 4) = acc;
    if (lane < 4) {
        const float* s = g_easum + (size_t)n * EAP;
        float4 ex;
        if (lane == 0)      ex = make_float4(s[0], s[1], s[2], s[3]);
        else if (lane == 1) ex = make_float4(s[4], s[5], s[6], s[7]);
        else if (lane == 2) ex = make_float4(s[8], s[9] + 1.f, 1.f, 0.f);
        else                ex = make_float4(0.f, 0.f, 0.f, 0.f);
        *(float4*)(g_agg + (size_t)n * KEXT + 128 + lane * 4) = ex;
    }
}

__global__ void prep_layer(const float* __restrict__ enc_w, const float* __restrict__ enc_b,
                           const float* __restrict__ w1,    const float* __restrict__ b1,
                           const float* __restrict__ gamma, const float* __restrict__ beta,
                           const float* __restrict__ mean,  const float* __restrict__ var,
                           const int* __restrict__ sli_p,   const int* __restrict__ slt_p) {
    int k = blockIdx.x;      // 0..143
    int c = threadIdx.x;     // 0..255
    if (k < 128) {
        g_w1ext[k * 256 + c] = w1[k * 256 + c];
    } else if (k < 139) {
        __shared__ float f[128];
        int j = k - 128;
        if (c < 128) {
            float fv;
            if (j < 9)       fv = enc_w[j * 128 + c];
            else if (j == 9) fv = enc_b[c];
            else             fv = (float)(*slt_p) * enc_w[(*sli_p) * 128 + c];
            f[c] = fv;
        }
        __syncthreads();
        float s = 0.f;
        const float* wb = w1 + 128 * 256 + c;
#pragma unroll 16
        for (int i = 0; i < 128; i++)
            s += f[i] * wb[i * 256];
        g_w1ext[k * 256 + c] = s;
    } else {
        g_w1ext[k * 256 + c] = 0.f;
    }
    if (k == 0) {
        float sc = gamma[c] * rsqrtf(var[c] + BN_EPS);
        g_scale[c] = sc;
        g_shift[c] = (b1[c] - mean[c]) * sc + beta[c];
    }
}

// Mini-GEMM: wf[t][k] = sum_i w2[k][i]*pwsum[i][t]; blocks 0-7 each do 32 k,
// block 8 does the bias fold. All 256 threads busy, smem-tiled.
__global__ void prep_pred(const float* __restrict__ w2, const float* __restrict__ b2,
                          const float* __restrict__ pw, const float* __restrict__ pb) {
    int b = blockIdx.x;
    int t = threadIdx.x;
    __shared__ float ps[128][NT + 1];
    for (int idx = t; idx < 128 * NT; idx += 256) {
        int j = idx / NT, tt = idx % NT;
        ps[j][tt] = __ldg(pw + j * NT + tt) + __ldg(pw + (j + 128) * NT + tt);
    }
    if (b < 8) {
        __shared__ float w[32][129];
        int k0 = b * 32;
        for (int idx = t; idx < 32 * 128; idx += 256) {
            int kk = idx >> 7, i = idx & 127;
            w[kk][i] = w2[(size_t)(k0 + kk) * 128 + i];
        }
        __syncthreads();
        int kk = t >> 3, tg = t & 7;   // 32 k x 8 t-groups (5 t each)
        float s[5] = {0.f, 0.f, 0.f, 0.f, 0.f};
        for (int i = 0; i < 128; i++) {
            float wv = w[kk][i];
#pragma unroll
            for (int u = 0; u < 5; u++) s[u] += wv * ps[i][tg * 5 + u];
        }
#pragma unroll
        for (int u = 0; u < 5; u++)
            g_wf[(tg * 5 + u) * 256 + k0 + kk] = s[u];
    } else {
        __shared__ float bsh[128];
        if (t < 128) bsh[t] = b2[t];
        __syncthreads();
        if (t < NT) {
            float s = 0.f;
#pragma unroll 8
            for (int i = 0; i < 128; i++) s += bsh[i] * ps[i][t];
            g_bf[t] = s + pb[t];
        }
    }
}

// ---------------- tensor-core GEMM (bf16 hi/lo split, fp32 accumulate) --------
__global__ void __launch_bounds__(256, 1)
gemm_tc(const float* __restrict__ A, const float* __restrict__ B,
        float* __restrict__ C, int M, int N, int K,
        const float* __restrict__ scale, const float* __restrict__ shift, int relu,
        const int* __restrict__ batchmap, float* __restrict__ pool) {
    __shared__ uint32_t Ah[2][8][APAD], Al[2][8][APAD];
    __shared__ uint32_t Bh[2][8][BPAD], Bl[2][8][BPAD];
    int bm = blockIdx.x * 128, bn = blockIdx.y * 128;
    int tid = threadIdx.x;
    int wid = tid >> 5, lane = tid & 31;
    int gid = lane >> 2, tig = lane & 3;
    int wm = (wid >> 2) * 64, wn = (wid & 3) * 32;

    int arow = tid >> 2, aq = tid & 3;
    int bkp = tid >> 5, bc4 = (tid & 31) * 4;

    float acc[4][4][4];
#pragma unroll
    for (int i = 0; i < 4; i++)
#pragma unroll
        for (int j = 0; j < 4; j++)
#pragma unroll
            for (int r = 0; r < 4; r++) acc[i][j][r] = 0.f;

    const float4 zero4 = make_float4(0.f, 0.f, 0.f, 0.f);
    float4 ra[2], rb[2];

    auto store_tiles = [&](int buf) {
#pragma unroll
        for (int i = 0; i < 2; i++) {
            uint32_t h0, l0, h1, l1;
            split2(ra[i].x, ra[i].y, h0, l0);
            split2(ra[i].z, ra[i].w, h1, l1);
            int r = arow + i * 64;
            Ah[buf][aq * 2][r] = h0;     Al[buf][aq * 2][r] = l0;
            Ah[buf][aq * 2 + 1][r] = h1; Al[buf][aq * 2 + 1][r] = l1;
        }
        uint32_t h[4], l[4];
        split2(rb[0].x, rb[1].x, h[0], l[0]);
        split2(rb[0].y, rb[1].y, h[1], l[1]);
        split2(rb[0].z, rb[1].z, h[2], l[2]);
        split2(rb[0].w, rb[1].w, h[3], l[3]);
        *(uint4*)&Bh[buf][bkp][bc4] = make_uint4(h[0], h[1], h[2], h[3]);
        *(uint4*)&Bl[buf][bkp][bc4] = make_uint4(l[0], l[1], l[2], l[3]);
    };

    {
        int gr0 = bm + arow, gr1 = bm + arow + 64;
        ra[0] = (gr0 < M) ? *(const float4*)(A + (size_t)gr0 * K + aq * 4) : zero4;
        ra[1] = (gr1 < M) ? *(const float4*)(A + (size_t)gr1 * K + aq * 4) : zero4;
        rb[0] = *(const float4*)(B + (size_t)(2 * bkp) * N + bn + bc4);
        rb[1] = *(const float4*)(B + (size_t)(2 * bkp + 1) * N + bn + bc4);
        store_tiles(0);
    }
    __syncthreads();

    int nch = K / 16;
    for (int c = 0; c < nch; c++) {
        int cur = c & 1;
        if (c + 1 < nch) {
            int k0 = (c + 1) * 16;
            int gr0 = bm + arow, gr1 = bm + arow + 64;
            ra[0] = (gr0 < M) ? *(const float4*)(A + (size_t)gr0 * K + k0 + aq * 4) : zero4;
            ra[1] = (gr1 < M) ? *(const float4*)(A + (size_t)gr1 * K + k0 + aq * 4) : zero4;
            rb[0] = *(const float4*)(B + (size_t)(k0 + 2 * bkp) * N + bn + bc4);
            rb[1] = *(const float4*)(B + (size_t)(k0 + 2 * bkp + 1) * N + bn + bc4);
        }
        {
            uint32_t ahi[4][4], alo[4][4];
#pragma unroll
            for (int mi = 0; mi < 4; mi++) {
                int r = wm + mi * 16 + gid;
                ahi[mi][0] = Ah[cur][tig][r];     alo[mi][0] = Al[cur][tig][r];
                ahi[mi][1] = Ah[cur][tig][r + 8]; alo[mi][1] = Al[cur][tig][r + 8];
                ahi[mi][2] = Ah[cur][tig + 4][r];     alo[mi][2] = Al[cur][tig + 4][r];
                ahi[mi][3] = Ah[cur][tig + 4][r + 8]; alo[mi][3] = Al[cur][tig + 4][r + 8];
            }
            uint32_t bhi[4][2], blo[4][2];
#pragma unroll
            for (int ni = 0; ni < 4; ni++) {
                int cc = wn + ni * 8 + gid;
                bhi[ni][0] = Bh[cur][tig][cc];     blo[ni][0] = Bl[cur][tig][cc];
                bhi[ni][1] = Bh[cur][tig + 4][cc]; blo[ni][1] = Bl[cur][tig + 4][cc];
            }
#pragma unroll
            for (int mi = 0; mi < 4; mi++)
#pragma unroll
                for (int ni = 0; ni < 4; ni++) {
                    mma_bf16(acc[mi][ni], ahi[mi], bhi[ni]);
                    mma_bf16(acc[mi][ni], alo[mi], bhi[ni]);
                    mma_bf16(acc[mi][ni], ahi[mi], blo[ni]);
                }
        }
        if (c + 1 < nch) {
            __syncthreads();
            store_tiles(1 - cur);
            __syncthreads();
        }
    }

#pragma unroll
    for (int ni = 0; ni < 4; ni++) {
        int col = bn + wn + ni * 8 + tig * 2;
        float s0 = 1.f, s1 = 1.f, t0 = 0.f, t1 = 0.f;
        if (scale) { s0 = __ldg(scale + col); s1 = __ldg(scale + col + 1); }
        if (shift) { t0 = __ldg(shift + col); t1 = __ldg(shift + col + 1); }
#pragma unroll
        for (int mi = 0; mi < 4; mi++) {
            int r0 = bm + wm + mi * 16 + gid;
            float2 v0 = make_float2(acc[mi][ni][0] * s0 + t0, acc[mi][ni][1] * s1 + t1);
            float2 v1 = make_float2(acc[mi][ni][2] * s0 + t0, acc[mi][ni][3] * s1 + t1);
            if (relu) {
                v0.x = fmaxf(v0.x, 0.f); v0.y = fmaxf(v0.y, 0.f);
                v1.x = fmaxf(v1.x, 0.f); v1.y = fmaxf(v1.y, 0.f);
            }
            if (batchmap) {
                if (r0 < M) {
                    int g = __ldg(batchmap + r0);
                    red_add_v2(pool + (size_t)g * 256 + col, v0);
                }
                if (r0 + 8 < M) {
                    int g = __ldg(batchmap + r0 + 8);
                    red_add_v2(pool + (size_t)g * 256 + col, v1);
                }
            } else {
                if (r0 < M)     *(float2*)(C + (size_t)r0 * N + col) = v0;
                if (r0 + 8 < M) *(float2*)(C + (size_t)(r0 + 8) * N + col) = v1;
            }
        }
    }
}

__global__ void pred2(float* __restrict__ out) {
    int g = blockIdx.x;
    int k = threadIdx.x;
    __shared__ float p[256];
    p[k] = g_poolz[g * 256 + k];
    __syncthreads();
    if (k < NT) {
        const float* wf = g_wf + k * 256;
        float s = 0.f;
#pragma unroll 16
        for (int i = 0; i < 256; i++) s += p[i] * wf[i];
        float cnt = fmaxf((float)g_cnt[g], 1.f);
        out[g * NT + k] = s / cnt + g_bf[k];
    }
}

// ---------------- launch -----------------------------------------------------
extern "C" void kernel_launch(void* const* d_in, const int* in_sizes, int n_in,
                              void* d_out, int out_size) {
    const int*   x        = (const int*)  d_in[0];
    const int*   ei       = (const int*)  d_in[1];
    const float* ea       = (const float*)d_in[2];
    const int*   batch    = (const int*)  d_in[3];
    const int*   sli      = (const int*)  d_in[4];
    const int*   slt      = (const int*)  d_in[5];
    const float* node_emb = (const float*)d_in[6];
    const float* L[2][10];
    for (int l = 0; l < 2; l++)
        for (int j = 0; j < 10; j++)
            L[l][j] = (const float*)d_in[7 + l * 10 + j];
    const float* pred_w = (const float*)d_in[27];
    const float* pred_b = (const float*)d_in[28];
    float* out = (float*)d_out;

    int N = in_sizes[0];
    int E = in_sizes[1] / 2;
    int B = (N + 255) / 256;

    float *p_agg, *p_w1ext, *p_z, *p_h, *p_scale, *p_shift, *p_poolz;
    cudaGetSymbolAddress((void**)&p_agg,   g_agg);
    cudaGetSymbolAddress((void**)&p_w1ext, g_w1ext);
    cudaGetSymbolAddress((void**)&p_z,     g_z);
    cudaGetSymbolAddress((void**)&p_h,     g_h);
    cudaGetSymbolAddress((void**)&p_scale, g_scale);
    cudaGetSymbolAddress((void**)&p_shift, g_shift);
    cudaGetSymbolAddress((void**)&p_poolz, g_poolz);

    zero_kernel<<<(N * EAP + 255) / 256, 256>>>(N);
    init_h0<<<(N * 32 + 255) / 256, 256>>>(x, node_emb, batch, N);
    edge_presum<<<(E + 255) / 256, 256>>>(ei, ea, E);
    prep_pred<<<9, 256>>>(L[1][8], L[1][9], pred_w, pred_b);

    // CSR build (once; reused by both layers)
    scan1<<<B, 256>>>(N);
    scan2<<<1, 256>>>(B);
    scan3<<<B, 256>>>(N, E);
    scatter<<<(E + 255) / 256, 256>>>(ei, E);

    for (int l = 0; l < 2; l++) {
        prep_layer<<<KEXT, 256>>>(L[l][0], L[l][1], L[l][2], L[l][3], L[l][4],
                                  L[l][5], L[l][6], L[l][7], sli, slt);
        aggregate<<<(N * 32 + 255) / 256, 256>>>(N);
        if (l == 0) {
            gemm_tc<<<dim3((N + 127) / 128, 2), 256>>>(
                p_agg, p_w1ext, p_z, N, 256, KEXT, p_scale, p_shift, 1, nullptr, nullptr);
            gemm_tc<<<dim3((N + 127) / 128, 1), 256>>>(
                p_z, L[0][8], p_h, N, 128, 256, nullptr, L[0][9], 1, nullptr, nullptr);
        } else {
            gemm_tc<<<dim3((N + 127) / 128, 2), 256>>>(
                p_agg, p_w1ext, p_z, N, 256, KEXT, p_scale, p_shift, 1, batch, p_poolz);
        }
    }

    pred2<<<NG, 256>>>(out);
}

// round 8
// speedup vs baseline: 2.8277x; 1.1057x over previous
#include <cuda_runtime.h>
#include <math.h>
#include <stdint.h>

#define H 128
#define KEXT 144
#define EAP 12            // easum row: 9 attrs, deg, cnt1, pad
#define NG 256
#define NT 40
#define MAXN 50048
#define MAXE 600064
#define BN_EPS 1e-5f
#define APAD 132
#define BPAD 136

// ---------------- scratch ----------------------------------------------------
__device__ float g_h[MAXN * H];
__device__ float g_agg[MAXN * KEXT];
__device__ float g_z[MAXN * 2 * H];
__device__ float g_easum[MAXN * EAP];
__device__ float g_w1ext[KEXT * 2 * H];
__device__ float g_umat[13 * 2 * H];
__device__ float g_poolz[NG * 2 * H];
__device__ float g_wf[NT * 2 * H];
__device__ float g_bf[NT];
__device__ int   g_cnt[NG];
__device__ int   g_off[MAXN + 1];
__device__ int   g_fill[MAXN];
__device__ int   g_csrc[MAXE];

// ---------------- helpers ---------------------------------------------------
__device__ __forceinline__ void red_add_v4(float* p, float4 v) {
    asm volatile("red.global.add.v4.f32 [%0], {%1,%2,%3,%4};"
                 :: "l"(p), "f"(v.x), "f"(v.y), "f"(v.z), "f"(v.w) : "memory");
}
__device__ __forceinline__ void red_add_v2(float* p, float2 v) {
    asm volatile("red.global.add.v2.f32 [%0], {%1,%2};"
                 :: "l"(p), "f"(v.x), "f"(v.y) : "memory");
}
__device__ __forceinline__ uint32_t pack2(float lo, float hi) {
    uint32_t r;
    asm("cvt.rn.bf16x2.f32 %0, %1, %2;" : "=r"(r) : "f"(hi), "f"(lo));
    return r;
}
__device__ __forceinline__ void split2(float f0, float f1, uint32_t& hi, uint32_t& lo) {
    hi = pack2(f0, f1);
    float h0 = __uint_as_float(hi << 16);
    float h1 = __uint_as_float(hi & 0xffff0000u);
    lo = pack2(f0 - h0, f1 - h1);
}
__device__ __forceinline__ void mma_bf16(float* d, const uint32_t* a, const uint32_t* b) {
    asm volatile("mma.sync.aligned.m16n8k16.row.col.f32.bf16.bf16.f32 "
                 "{%0,%1,%2,%3},{%4,%5,%6,%7},{%8,%9},{%0,%1,%2,%3};"
                 : "+f"(d[0]), "+f"(d[1]), "+f"(d[2]), "+f"(d[3])
                 : "r"(a[0]), "r"(a[1]), "r"(a[2]), "r"(a[3]),
                   "r"(b[0]), "r"(b[1]));
}

// ---------------- small kernels ----------------------------------------------
__global__ void zero_kernel(int N) {
    int i = blockIdx.x * blockDim.x + threadIdx.x;
    if (i < N * EAP)    g_easum[i] = 0.f;
    if (i < NG * 2 * H) g_poolz[i] = 0.f;
    if (i < NG)         g_cnt[i] = 0;
    if (i < N)          g_fill[i] = 0;
}

__global__ void count_nodes(const int* __restrict__ batch, int N) {
    int n = blockIdx.x * blockDim.x + threadIdx.x;
    if (n < N) atomicAdd(&g_cnt[batch[n]], 1);
}

// per-edge: accumulate attrs, deg, and cnt1 (= sum of x[src]) per dst
__global__ void edge_presum(const int* __restrict__ ei, const float* __restrict__ ea,
                            const int* __restrict__ x, int E) {
    int e = blockIdx.x * blockDim.x + threadIdx.x;
    if (e >= E) return;
    int d = __ldg(ei + e);
    int s = __ldg(ei + E + e);
    const float* a = ea + (size_t)e * 9;
    float4 v0 = make_float4(a[0], a[1], a[2], a[3]);
    float4 v1 = make_float4(a[4], a[5], a[6], a[7]);
    float4 v2 = make_float4(a[8], 1.f, (float)__ldg(x + s), 0.f);
    float* p = g_easum + (size_t)d * EAP;
    red_add_v4(p, v0);
    red_add_v4(p + 4, v1);
    red_add_v4(p + 8, v2);
}

// single-block exclusive scan of deg -> g_off
__global__ void scan_all(int N, int E) {
    int tid = threadIdx.x;
    int chunk = (N + 1023) / 1024;
    int start = tid * chunk;
    int end = min(start + chunk, N);
    int s = 0;
    for (int i = start; i < end; i++) s += (int)g_easum[(size_t)i * EAP + 9];
    __shared__ int sm[1024];
    sm[tid] = s;
    __syncthreads();
#pragma unroll
    for (int off = 1; off < 1024; off <<= 1) {
        int v = (tid >= off) ? sm[tid - off] : 0;
        __syncthreads();
        sm[tid] += v;
        __syncthreads();
    }
    int run = sm[tid] - s;    // exclusive prefix
    for (int i = start; i < end; i++) {
        g_off[i] = run;
        run += (int)g_easum[(size_t)i * EAP + 9];
    }
    if (tid == 0) g_off[N] = E;
}

__global__ void scatter(const int* __restrict__ ei, int E) {
    int e = blockIdx.x * blockDim.x + threadIdx.x;
    if (e >= E) return;
    int d = __ldg(ei + e);
    int slot = atomicAdd(&g_fill[d], 1);
    g_csrc[g_off[d] + slot] = __ldg(ei + E + e);
}

// layer-1 neighbor gather (warp per node)
__global__ void aggregate(int N) {
    int t = blockIdx.x * blockDim.x + threadIdx.x;
    int n = t >> 5;
    if (n >= N) return;
    int lane = t & 31;
    float4 acc = *(const float4*)(g_h + (size_t)n * H + lane * 4);
    int beg = g_off[n], end = g_off[n + 1];
    int e = beg;
    for (; e + 4 <= end; e += 4) {
        int s0 = __ldg(g_csrc + e),     s1 = __ldg(g_csrc + e + 1);
        int s2 = __ldg(g_csrc + e + 2), s3 = __ldg(g_csrc + e + 3);
        float4 v0 = *(const float4*)(g_h + (size_t)s0 * H + lane * 4);
        float4 v1 = *(const float4*)(g_h + (size_t)s1 * H + lane * 4);
        float4 v2 = *(const float4*)(g_h + (size_t)s2 * H + lane * 4);
        float4 v3 = *(const float4*)(g_h + (size_t)s3 * H + lane * 4);
        acc.x += v0.x + v1.x + v2.x + v3.x;
        acc.y += v0.y + v1.y + v2.y + v3.y;
        acc.z += v0.z + v1.z + v2.z + v3.z;
        acc.w += v0.w + v1.w + v2.w + v3.w;
    }
    for (; e < end; e++) {
        int s0 = __ldg(g_csrc + e);
        float4 v0 = *(const float4*)(g_h + (size_t)s0 * H + lane * 4);
        acc.x += v0.x; acc.y += v0.y; acc.z += v0.z; acc.w += v0.w;
    }
    *(float4*)(g_agg + (size_t)n * KEXT + lane * 4) = acc;
    if (lane < 4) {
        const float* s = g_easum + (size_t)n * EAP;
        float4 ex;
        if (lane == 0)      ex = make_float4(s[0], s[1], s[2], s[3]);
        else if (lane == 1) ex = make_float4(s[4], s[5], s[6], s[7]);
        else if (lane == 2) ex = make_float4(s[8], s[9] + 1.f, 1.f, 0.f);
        else                ex = make_float4(0.f, 0.f, 0.f, 0.f);
        *(float4*)(g_agg + (size_t)n * KEXT + 128 + lane * 4) = ex;
    }
}

// w1ext for layer 1 with BN folded (scale into all rows, shift into row 138)
__global__ void prep_layer(const float* __restrict__ enc_w, const float* __restrict__ enc_b,
                           const float* __restrict__ w1,    const float* __restrict__ b1,
                           const float* __restrict__ gamma, const float* __restrict__ beta,
                           const float* __restrict__ mean,  const float* __restrict__ var,
                           const int* __restrict__ sli_p,   const int* __restrict__ slt_p) {
    int k = blockIdx.x;      // 0..143
    int c = threadIdx.x;     // 0..255
    float sc = gamma[c] * rsqrtf(var[c] + BN_EPS);
    float sh = (b1[c] - mean[c]) * sc + beta[c];
    if (k < 128) {
        g_w1ext[k * 256 + c] = w1[k * 256 + c] * sc;
    } else if (k < 139) {
        __shared__ float f[128];
        int j = k - 128;
        if (c < 128) {
            float fv;
            if (j < 9)       fv = enc_w[j * 128 + c];
            else if (j == 9) fv = enc_b[c];
            else             fv = (float)(*slt_p) * enc_w[(*sli_p) * 128 + c];
            f[c] = fv;
        }
        __syncthreads();
        float s = 0.f;
        const float* wb = w1 + 128 * 256 + c;
#pragma unroll 16
        for (int i = 0; i < 128; i++)
            s += f[i] * wb[i * 256];
        g_w1ext[k * 256 + c] = s * sc + (k == 138 ? sh : 0.f);
    } else {
        g_w1ext[k * 256 + c] = 0.f;
    }
}

// layer-0 rank-13 basis with BN folded
__global__ void prep_aff(const float* __restrict__ emb,
                         const float* __restrict__ enc_w, const float* __restrict__ enc_b,
                         const float* __restrict__ w1,    const float* __restrict__ b1,
                         const float* __restrict__ gamma, const float* __restrict__ beta,
                         const float* __restrict__ mean,  const float* __restrict__ var,
                         const int* __restrict__ sli_p,   const int* __restrict__ slt_p) {
    int r = blockIdx.x;      // 0..12
    int c = threadIdx.x;     // 0..255
    __shared__ float f[128];
    if (c < 128) {
        float fv;
        if (r < 2)        fv = emb[r * 128 + c];
        else if (r < 11)  fv = enc_w[(r - 2) * 128 + c];
        else if (r == 11) fv = enc_b[c];
        else              fv = (float)(*slt_p) * enc_w[(*sli_p) * 128 + c];
        f[c] = fv;
    }
    __syncthreads();
    int base = (r < 2) ? 0 : 128;
    float s = 0.f;
    const float* wb = w1 + base * 256 + c;
#pragma unroll 16
    for (int i = 0; i < 128; i++)
        s += f[i] * wb[i * 256];
    float sc = gamma[c] * rsqrtf(var[c] + BN_EPS);
    float sh = (b1[c] - mean[c]) * sc + beta[c];
    g_umat[r * 256 + c] = s * sc + (r == 12 ? sh : 0.f);
}

// z0[n] = relu(sum_r coef[n][r] * U[r])  (layer-0 GEMM1 + aggregate, collapsed)
__global__ void __launch_bounds__(256)
node_affine(const int* __restrict__ x, int N) {
    __shared__ float Us[13][256];
    __shared__ float coef[64][13];
    int tid = threadIdx.x;
    for (int idx = tid; idx < 13 * 256; idx += 256)
        Us[idx >> 8][idx & 255] = g_umat[idx];
    int n0 = blockIdx.x * 64;
    if (tid < 64) {
        int n = n0 + tid;
        if (n < N) {
            const float* s = g_easum + (size_t)n * EAP;
            float deg = s[9], cnt1 = s[10];
            int xv = __ldg(x + n);
            coef[tid][0] = deg - cnt1 + (xv == 0 ? 1.f : 0.f);
            coef[tid][1] = cnt1 + (xv == 1 ? 1.f : 0.f);
#pragma unroll
            for (int j = 0; j < 9; j++) coef[tid][2 + j] = s[j];
            coef[tid][11] = deg + 1.f;
            coef[tid][12] = 1.f;
        }
    }
    __syncthreads();
    float u[13];
#pragma unroll
    for (int r = 0; r < 13; r++) u[r] = Us[r][tid];
    int nmax = min(64, N - n0);
    int nl = 0;
    for (; nl + 2 <= nmax; nl += 2) {
        float s0 = 0.f, s1 = 0.f;
#pragma unroll
        for (int r = 0; r < 13; r++) {
            s0 += coef[nl][r] * u[r];
            s1 += coef[nl + 1][r] * u[r];
        }
        g_z[(size_t)(n0 + nl) * 256 + tid] = fmaxf(s0, 0.f);
        g_z[(size_t)(n0 + nl + 1) * 256 + tid] = fmaxf(s1, 0.f);
    }
    if (nl < nmax) {
        float s0 = 0.f;
#pragma unroll
        for (int r = 0; r < 13; r++) s0 += coef[nl][r] * u[r];
        g_z[(size_t)(n0 + nl) * 256 + tid] = fmaxf(s0, 0.f);
    }
}

// wf fold: 257 blocks (256 k-columns + 1 bias), warp handles 5 t outputs
__global__ void prep_pred(const float* __restrict__ w2, const float* __restrict__ b2,
                          const float* __restrict__ pw, const float* __restrict__ pb) {
    int k = blockIdx.x;
    int tid = threadIdx.x;
    __shared__ float ws[128];
    if (tid < 128) ws[tid] = (k < 256) ? w2[(size_t)k * 128 + tid] : b2[tid];
    __syncthreads();
    int w = tid >> 5, lane = tid & 31;
    float acc[5] = {0.f, 0.f, 0.f, 0.f, 0.f};
#pragma unroll
    for (int j = 0; j < 4; j++) {
        int i = j * 32 + lane;
        float wv = ws[i];
#pragma unroll
        for (int u = 0; u < 5; u++) {
            int t = w * 5 + u;
            acc[u] += wv * (__ldg(pw + i * NT + t) + __ldg(pw + (i + 128) * NT + t));
        }
    }
#pragma unroll
    for (int u = 0; u < 5; u++)
#pragma unroll
        for (int off = 16; off; off >>= 1)
            acc[u] += __shfl_down_sync(0xffffffffu, acc[u], off);
    if (lane == 0) {
#pragma unroll
        for (int u = 0; u < 5; u++) {
            int t = w * 5 + u;
            if (k < 256) g_wf[t * 256 + k] = acc[u];
            else         g_bf[t] = acc[u] + pb[t];
        }
    }
}

// ---------------- tensor-core GEMM (bf16 hi/lo split, fp32 accumulate) --------
__global__ void __launch_bounds__(256, 2)
gemm_tc(const float* __restrict__ A, const float* __restrict__ B,
        float* __restrict__ C, int M, int N, int K,
        const float* __restrict__ shift, int relu,
        const int* __restrict__ batchmap, float* __restrict__ pool) {
    __shared__ uint32_t Ah[2][8][APAD], Al[2][8][APAD];
    __shared__ uint32_t Bh[2][8][BPAD], Bl[2][8][BPAD];
    int bm = blockIdx.x * 128, bn = blockIdx.y * 128;
    int tid = threadIdx.x;
    int wid = tid >> 5, lane = tid & 31;
    int gid = lane >> 2, tig = lane & 3;
    int wm = (wid >> 2) * 64, wn = (wid & 3) * 32;

    int arow = tid >> 2, aq = tid & 3;
    int bkp = tid >> 5, bc4 = (tid & 31) * 4;

    float acc[4][4][4];
#pragma unroll
    for (int i = 0; i < 4; i++)
#pragma unroll
        for (int j = 0; j < 4; j++)
#pragma unroll
            for (int r = 0; r < 4; r++) acc[i][j][r] = 0.f;

    const float4 zero4 = make_float4(0.f, 0.f, 0.f, 0.f);
    float4 ra[2], rb[2];

    auto store_tiles = [&](int buf) {
#pragma unroll
        for (int i = 0; i < 2; i++) {
            uint32_t h0, l0, h1, l1;
            split2(ra[i].x, ra[i].y, h0, l0);
            split2(ra[i].z, ra[i].w, h1, l1);
            int r = arow + i * 64;
            Ah[buf][aq * 2][r] = h0;     Al[buf][aq * 2][r] = l0;
            Ah[buf][aq * 2 + 1][r] = h1; Al[buf][aq * 2 + 1][r] = l1;
        }
        uint32_t h[4], l[4];
        split2(rb[0].x, rb[1].x, h[0], l[0]);
        split2(rb[0].y, rb[1].y, h[1], l[1]);
        split2(rb[0].z, rb[1].z, h[2], l[2]);
        split2(rb[0].w, rb[1].w, h[3], l[3]);
        *(uint4*)&Bh[buf][bkp][bc4] = make_uint4(h[0], h[1], h[2], h[3]);
        *(uint4*)&Bl[buf][bkp][bc4] = make_uint4(l[0], l[1], l[2], l[3]);
    };

    {
        int gr0 = bm + arow, gr1 = bm + arow + 64;
        ra[0] = (gr0 < M) ? *(const float4*)(A + (size_t)gr0 * K + aq * 4) : zero4;
        ra[1] = (gr1 < M) ? *(const float4*)(A + (size_t)gr1 * K + aq * 4) : zero4;
        rb[0] = *(const float4*)(B + (size_t)(2 * bkp) * N + bn + bc4);
        rb[1] = *(const float4*)(B + (size_t)(2 * bkp + 1) * N + bn + bc4);
        store_tiles(0);
    }
    __syncthreads();

    int nch = K / 16;
    for (int c = 0; c < nch; c++) {
        int cur = c & 1;
        if (c + 1 < nch) {
            int k0 = (c + 1) * 16;
            int gr0 = bm + arow, gr1 = bm + arow + 64;
            ra[0] = (gr0 < M) ? *(const float4*)(A + (size_t)gr0 * K + k0 + aq * 4) : zero4;
            ra[1] = (gr1 < M) ? *(const float4*)(A + (size_t)gr1 * K + k0 + aq * 4) : zero4;
            rb[0] = *(const float4*)(B + (size_t)(k0 + 2 * bkp) * N + bn + bc4);
            rb[1] = *(const float4*)(B + (size_t)(k0 + 2 * bkp + 1) * N + bn + bc4);
        }
        {
            uint32_t ahi[4][4], alo[4][4];
#pragma unroll
            for (int mi = 0; mi < 4; mi++) {
                int r = wm + mi * 16 + gid;
                ahi[mi][0] = Ah[cur][tig][r];     alo[mi][0] = Al[cur][tig][r];
                ahi[mi][1] = Ah[cur][tig][r + 8]; alo[mi][1] = Al[cur][tig][r + 8];
                ahi[mi][2] = Ah[cur][tig + 4][r];     alo[mi][2] = Al[cur][tig + 4][r];
                ahi[mi][3] = Ah[cur][tig + 4][r + 8]; alo[mi][3] = Al[cur][tig + 4][r + 8];
            }
            uint32_t bhi[4][2], blo[4][2];
#pragma unroll
            for (int ni = 0; ni < 4; ni++) {
                int cc = wn + ni * 8 + gid;
                bhi[ni][0] = Bh[cur][tig][cc];     blo[ni][0] = Bl[cur][tig][cc];
                bhi[ni][1] = Bh[cur][tig + 4][cc]; blo[ni][1] = Bl[cur][tig + 4][cc];
            }
#pragma unroll
            for (int mi = 0; mi < 4; mi++)
#pragma unroll
                for (int ni = 0; ni < 4; ni++) {
                    mma_bf16(acc[mi][ni], ahi[mi], bhi[ni]);
                    mma_bf16(acc[mi][ni], alo[mi], bhi[ni]);
                    mma_bf16(acc[mi][ni], ahi[mi], blo[ni]);
                }
        }
        if (c + 1 < nch) {
            __syncthreads();
            store_tiles(1 - cur);
            __syncthreads();
        }
    }

#pragma unroll
    for (int ni = 0; ni < 4; ni++) {
        int col = bn + wn + ni * 8 + tig * 2;
        float t0 = 0.f, t1 = 0.f;
        if (shift) { t0 = __ldg(shift + col); t1 = __ldg(shift + col + 1); }
#pragma unroll
        for (int mi = 0; mi < 4; mi++) {
            int r0 = bm + wm + mi * 16 + gid;
            float2 v0 = make_float2(acc[mi][ni][0] + t0, acc[mi][ni][1] + t1);
            float2 v1 = make_float2(acc[mi][ni][2] + t0, acc[mi][ni][3] + t1);
            if (relu) {
                v0.x = fmaxf(v0.x, 0.f); v0.y = fmaxf(v0.y, 0.f);
                v1.x = fmaxf(v1.x, 0.f); v1.y = fmaxf(v1.y, 0.f);
            }
            if (batchmap) {
                if (r0 < M) {
                    int g = __ldg(batchmap + r0);
                    red_add_v2(pool + (size_t)g * 256 + col, v0);
                }
                if (r0 + 8 < M) {
                    int g = __ldg(batchmap + r0 + 8);
                    red_add_v2(pool + (size_t)g * 256 + col, v1);
                }
            } else {
                if (r0 < M)     *(float2*)(C + (size_t)r0 * N + col) = v0;
                if (r0 + 8 < M) *(float2*)(C + (size_t)(r0 + 8) * N + col) = v1;
            }
        }
    }
}

__global__ void pred2(float* __restrict__ out) {
    int g = blockIdx.x;
    int k = threadIdx.x;
    __shared__ float p[256];
    p[k] = g_poolz[g * 256 + k];
    __syncthreads();
    if (k < NT) {
        const float* wf = g_wf + k * 256;
        float s = 0.f;
#pragma unroll 16
        for (int i = 0; i < 256; i++) s += p[i] * wf[i];
        float cnt = fmaxf((float)g_cnt[g], 1.f);
        out[g * NT + k] = s / cnt + g_bf[k];
    }
}

// ---------------- launch -----------------------------------------------------
extern "C" void kernel_launch(void* const* d_in, const int* in_sizes, int n_in,
                              void* d_out, int out_size) {
    const int*   x        = (const int*)  d_in[0];
    const int*   ei       = (const int*)  d_in[1];
    const float* ea       = (const float*)d_in[2];
    const int*   batch    = (const int*)  d_in[3];
    const int*   sli      = (const int*)  d_in[4];
    const int*   slt      = (const int*)  d_in[5];
    const float* node_emb = (const float*)d_in[6];
    const float* L[2][10];
    for (int l = 0; l < 2; l++)
        for (int j = 0; j < 10; j++)
            L[l][j] = (const float*)d_in[7 + l * 10 + j];
    const float* pred_w = (const float*)d_in[27];
    const float* pred_b = (const float*)d_in[28];
    float* out = (float*)d_out;

    int N = in_sizes[0];
    int E = in_sizes[1] / 2;

    float *p_agg, *p_w1ext, *p_z, *p_h, *p_poolz;
    cudaGetSymbolAddress((void**)&p_agg,   g_agg);
    cudaGetSymbolAddress((void**)&p_w1ext, g_w1ext);
    cudaGetSymbolAddress((void**)&p_z,     g_z);
    cudaGetSymbolAddress((void**)&p_h,     g_h);
    cudaGetSymbolAddress((void**)&p_poolz, g_poolz);

    zero_kernel<<<(N * EAP + 255) / 256, 256>>>(N);
    count_nodes<<<(N + 255) / 256, 256>>>(batch, N);
    edge_presum<<<(E + 255) / 256, 256>>>(ei, ea, x, E);
    prep_pred<<<257, 256>>>(L[1][8], L[1][9], pred_w, pred_b);
    prep_aff<<<13, 256>>>(node_emb, L[0][0], L[0][1], L[0][2], L[0][3], L[0][4],
                          L[0][5], L[0][6], L[0][7], sli, slt);
    scan_all<<<1, 1024>>>(N, E);
    scatter<<<(E + 255) / 256, 256>>>(ei, E);

    // layer 0: rank-13 affine replaces aggregate+GEMM1
    node_affine<<<(N + 63) / 64, 256>>>(x, N);
    // h1 = relu(z0 @ w2_0 + b2_0)
    gemm_tc<<<dim3((N + 127) / 128, 1), 256>>>(
        p_z, L[0][8], p_h, N, 128, 256, L[0][9], 1, nullptr, nullptr);

    // layer 1
    prep_layer<<<KEXT, 256>>>(L[1][0], L[1][1], L[1][2], L[1][3], L[1][4],
                              L[1][5], L[1][6], L[1][7], sli, slt);
    aggregate<<<(N * 32 + 255) / 256, 256>>>(N);
    gemm_tc<<<dim3((N + 127) / 128, 2), 256>>>(
        p_agg, p_w1ext, nullptr, N, 256, KEXT, nullptr, 1, batch, p_poolz);

    pred2<<<NG, 256>>>(out);
}